// round 1
// baseline (speedup 1.0000x reference)
#include <cuda_runtime.h>
#include <math.h>

// ---------------- problem constants ----------------
#define MB    32      // meta-batch = batch(2) * heads(16)
#define SEQ   4096
#define DH    64      // head dim
#define NB    128     // seq / 32 blocks
#define BS    32      // block size
#define NSEL  512     // NUM_BLOCKS
#define HDIM  1024
#define MROWS 8192    // batch * seq

// ---------------- scratch (device globals; no allocation allowed) ----------------
__device__ float    g_Q[(size_t)MB*SEQ*DH];
__device__ float    g_K[(size_t)MB*SEQ*DH];
__device__ float    g_V[(size_t)MB*SEQ*DH];
__device__ float    g_Qh[MB*NB*DH];
__device__ float    g_Kh[MB*NB*DH];
__device__ float    g_Vh[MB*NB*DH];
__device__ float    g_tc[MB*NB];
__device__ float    g_ll[MB*NB*NB];      // masked low-res logits
__device__ float    g_lrn[MB*NB*NB];     // lrn (logit - rowmax + band)
__device__ float    g_rowmax[MB*NB];
__device__ unsigned g_thrkey[MB];
__device__ int      g_selidx[MB*NSEL];
__device__ int      g_selcnt[MB];
__device__ unsigned g_maxblk[MB*NB*BS];  // ordered-uint encoded scatter-max
__device__ float    g_hiout[(size_t)MB*SEQ*DH];
__device__ float    g_hinorm[MB*SEQ];
__device__ float    g_lowout[MB*NB*DH];
__device__ float    g_lownorm[MB*NB];

// order-preserving float <-> uint mapping
__device__ __forceinline__ unsigned fkey(float f) {
    unsigned u = __float_as_uint(f);
    return (u & 0x80000000u) ? ~u : (u | 0x80000000u);
}
__device__ __forceinline__ float fdecode(unsigned k) {
    unsigned u = (k & 0x80000000u) ? (k & 0x7FFFFFFFu) : ~k;
    return __uint_as_float(u);
}

// ---------------- K1: QKV projection GEMM  out = X @ W^T + b, masked, head-split ----------------
// X: [8192,1024], W: [1024,1024] row-major (both K-contiguous). 128x128 tile, 8x8/thread.
__global__ __launch_bounds__(256) void k_gemm(
    const float* __restrict__ X, const float* __restrict__ W,
    const float* __restrict__ bias, const float* __restrict__ am,
    float* __restrict__ out)
{
    __shared__ float As[8][132];
    __shared__ float Bs[8][132];
    int tid = threadIdx.x;
    int tx = tid & 15, ty = tid >> 4;
    int m0 = blockIdx.y * 128, n0 = blockIdx.x * 128;

    float acc[8][8];
    #pragma unroll
    for (int i = 0; i < 8; i++)
        #pragma unroll
        for (int j = 0; j < 8; j++) acc[i][j] = 0.0f;

    int r = tid >> 1, c = (tid & 1) * 4;
    const float* Xp = X + (size_t)(m0 + r) * HDIM + c;
    const float* Wp = W + (size_t)(n0 + r) * HDIM + c;

    for (int k0 = 0; k0 < HDIM; k0 += 8) {
        float4 xa = *(const float4*)(Xp + k0);
        float4 wb = *(const float4*)(Wp + k0);
        As[c+0][r] = xa.x; As[c+1][r] = xa.y; As[c+2][r] = xa.z; As[c+3][r] = xa.w;
        Bs[c+0][r] = wb.x; Bs[c+1][r] = wb.y; Bs[c+2][r] = wb.z; Bs[c+3][r] = wb.w;
        __syncthreads();
        #pragma unroll
        for (int kk = 0; kk < 8; kk++) {
            float a[8], b[8];
            *(float4*)(a)     = *(const float4*)&As[kk][ty*8];
            *(float4*)(a + 4) = *(const float4*)&As[kk][ty*8 + 4];
            *(float4*)(b)     = *(const float4*)&Bs[kk][tx*8];
            *(float4*)(b + 4) = *(const float4*)&Bs[kk][tx*8 + 4];
            #pragma unroll
            for (int i = 0; i < 8; i++)
                #pragma unroll
                for (int j = 0; j < 8; j++)
                    acc[i][j] += a[i] * b[j];
        }
        __syncthreads();
    }

    #pragma unroll
    for (int i = 0; i < 8; i++) {
        int m = m0 + ty*8 + i;
        int b_ = m >> 12, s = m & 4095;
        #pragma unroll
        for (int j = 0; j < 8; j++) {
            int n = n0 + tx*8 + j;
            int h = n >> 6, e = n & 63;
            // jax tile semantics: mask row mb -> am[mb % 2]; mb = b_*16+h -> mb%2 = h&1
            float maskv = 1.0f + am[(h & 1) * SEQ + s] / 10000.0f;
            int mb = b_ * 16 + h;
            out[((size_t)mb * SEQ + s) * DH + e] = (acc[i][j] + bias[n]) * maskv;
        }
    }
}

// ---------------- K2: block means + token counts ----------------
__global__ void k_stats(const float* __restrict__ am) {
    int mb = blockIdx.y, i = blockIdx.x, e = threadIdx.x; // 64 threads
    float tc = 0.0f;
    int amb = (mb & 1) * SEQ + i * BS;
    for (int t = 0; t < BS; t++) tc += 1.0f + am[amb + t] / 10000.0f;
    float den = tc + 1e-6f;
    const float* Qp = g_Q + ((size_t)mb * SEQ + i * BS) * DH + e;
    const float* Kp = g_K + ((size_t)mb * SEQ + i * BS) * DH + e;
    const float* Vp = g_V + ((size_t)mb * SEQ + i * BS) * DH + e;
    float sq = 0, sk = 0, sv = 0;
    for (int t = 0; t < BS; t++) { sq += Qp[t*DH]; sk += Kp[t*DH]; sv += Vp[t*DH]; }
    int o = (mb * NB + i) * DH + e;
    g_Qh[o] = sq / den; g_Kh[o] = sk / den; g_Vh[o] = sv / den;
    if (e == 0) g_tc[mb * NB + i] = tc;
}

// ---------------- K3: low-res logits, row max, lrn (band added) ----------------
__global__ __launch_bounds__(128) void k_lowlogit() {
    int mb = blockIdx.x, i = threadIdx.x;
    __shared__ float sK[NB * DH];   // 32KB
    __shared__ float sTc[NB];
    for (int t = i; t < NB * DH; t += 128) sK[t] = g_Kh[mb * NB * DH + t];
    if (i < NB) sTc[i] = g_tc[mb * NB + i];
    __syncthreads();

    float qr[DH];
    #pragma unroll
    for (int k = 0; k < DH; k++) qr[k] = g_Qh[(mb * NB + i) * DH + k];

    float row[NB];
    float rmax = -INFINITY;
    for (int j = 0; j < NB; j++) {
        float d = 0.0f;
        #pragma unroll
        for (int k = 0; k < DH; k++) d += qr[k] * sK[j * DH + k];
        d *= 0.125f;                 // 1/sqrt(64)
        row[j] = d;
        rmax = fmaxf(rmax, d);       // max BEFORE mask subtraction (matches reference)
    }
    g_rowmax[mb * NB + i] = rmax;
    float tci = sTc[i];
    for (int j = 0; j < NB; j++) {
        float ll = row[j];
        if (tci * sTc[j] < 0.5f) ll -= 10000.0f;
        float lr = ll - rmax;
        int dd = i - j; if (dd < 0) dd = -dd;
        if (dd <= 1) lr += 5000.0f;  // DIAG_N=3 band
        g_ll [(mb * NB + i) * NB + j] = ll;
        g_lrn[(mb * NB + i) * NB + j] = lr;
    }
}

// ---------------- K4: top-512 selection via bitwise binary search on float keys ----------------
__global__ __launch_bounds__(256) void k_topk() {
    int mb = blockIdx.x, tid = threadIdx.x;
    const float* base = g_lrn + mb * NB * NB;
    __shared__ unsigned sred[256];
    unsigned lo = 0, hi = 0xFFFFFFFFu;
    while (lo < hi) {
        unsigned mid = (unsigned)(((unsigned long long)lo + (unsigned long long)hi + 1ull) >> 1);
        unsigned c = 0;
        for (int idx = tid; idx < NB * NB; idx += 256) c += (fkey(base[idx]) >= mid) ? 1u : 0u;
        sred[tid] = c; __syncthreads();
        for (int off = 128; off; off >>= 1) { if (tid < off) sred[tid] += sred[tid + off]; __syncthreads(); }
        unsigned cnt = sred[0]; __syncthreads();
        if (cnt >= NSEL) lo = mid; else hi = mid - 1;
    }
    if (tid == 0) g_thrkey[mb] = lo;
    for (int idx = tid; idx < NB * NB; idx += 256) {
        if (fkey(base[idx]) >= lo) {
            int p = atomicAdd(&g_selcnt[mb], 1);
            if (p < NSEL) g_selidx[mb * NSEL + p] = idx;
        }
    }
}

// ---------------- K5: hi-branch pass 1 — per-query-row scatter max over selected blocks ----------------
__global__ __launch_bounds__(256) void k_himax() {
    int mb = blockIdx.y, p = blockIdx.x, tid = threadIdx.x;
    int cnt = g_selcnt[mb]; if (cnt > NSEL) cnt = NSEL;
    if (p >= cnt) return;
    int idx = g_selidx[mb * NSEL + p];
    int qb = idx >> 7, kb = idx & 127;
    __shared__ float sQ[BS * 65], sK[BS * 65], sL[BS * 33];
    const float* Qg = g_Q + ((size_t)mb * SEQ + qb * BS) * DH;
    const float* Kg = g_K + ((size_t)mb * SEQ + kb * BS) * DH;
    for (int t = tid; t < BS * DH; t += 256) {
        int r = t >> 6, cc = t & 63;
        sQ[r * 65 + cc] = Qg[t];
        sK[r * 65 + cc] = Kg[t];
    }
    __syncthreads();
    for (int l = tid; l < BS * BS; l += 256) {
        int q = l >> 5, k = l & 31;
        float d = 0.0f;
        #pragma unroll
        for (int e = 0; e < DH; e++) d += sK[k * 65 + e] * sQ[q * 65 + e];
        sL[k * 33 + q] = d * 0.125f;
    }
    __syncthreads();
    if (tid < BS) {
        int q = tid; float m = -INFINITY;
        for (int k = 0; k < BS; k++) m = fmaxf(m, sL[k * 33 + q]); // unmasked max (matches ref)
        atomicMax(&g_maxblk[(mb * NB + qb) * BS + q], fkey(m));
    }
}

// ---------------- K6: hi-branch pass 2 — exp + A@V scatter-add + normalizer ----------------
__global__ __launch_bounds__(256) void k_hiout(const float* __restrict__ am) {
    int mb = blockIdx.y, p = blockIdx.x, tid = threadIdx.x;
    int cnt = g_selcnt[mb]; if (cnt > NSEL) cnt = NSEL;
    if (p >= cnt) return;
    int idx = g_selidx[mb * NSEL + p];
    int qb = idx >> 7, kb = idx & 127;
    __shared__ float sQ[BS * 65], sK[BS * 65], sV[BS * 68], sA[BS * 33], sMq[BS], sMk[BS];
    const float* Qg = g_Q + ((size_t)mb * SEQ + qb * BS) * DH;
    const float* Kg = g_K + ((size_t)mb * SEQ + kb * BS) * DH;
    const float* Vg = g_V + ((size_t)mb * SEQ + kb * BS) * DH;
    for (int t = tid; t < BS * DH; t += 256) {
        int r = t >> 6, cc = t & 63;
        sQ[r * 65 + cc] = Qg[t];
        sK[r * 65 + cc] = Kg[t];
        sV[r * 68 + cc] = Vg[t];
    }
    if (tid < BS) {
        sMq[tid] = fdecode(g_maxblk[(mb * NB + qb) * BS + tid]);
        sMk[tid] = 1.0f + am[(mb & 1) * SEQ + kb * BS + tid] / 10000.0f;
    }
    __syncthreads();
    for (int l = tid; l < BS * BS; l += 256) {
        int q = l >> 5, k = l & 31;
        float d = 0.0f;
        #pragma unroll
        for (int e = 0; e < DH; e++) d += sK[k * 65 + e] * sQ[q * 65 + e];
        d = d * 0.125f - sMq[q] - 10000.0f * (1.0f - sMk[k]);
        sA[k * 33 + q] = __expf(d);
    }
    __syncthreads();
    int q = tid >> 3, g = tid & 7, e0 = g * 8;
    float acc[8] = {0,0,0,0,0,0,0,0};
    float nsum = 0.0f;
    for (int k = 0; k < BS; k++) {
        float a = sA[k * 33 + q];
        nsum += a;
        #pragma unroll
        for (int j = 0; j < 8; j++) acc[j] += a * sV[k * 68 + e0 + j];
    }
    float* dst = g_hiout + ((size_t)mb * SEQ + qb * BS + q) * DH + e0;
    #pragma unroll
    for (int j = 0; j < 8; j++) atomicAdd(dst + j, acc[j]);
    if (g == 0) atomicAdd(&g_hinorm[mb * SEQ + qb * BS + q], nsum);
}

// ---------------- K7: low-res branch (selected blocks suppressed) ----------------
__global__ __launch_bounds__(128) void k_low() {
    int mb = blockIdx.y, i = blockIdx.x, j = threadIdx.x;
    __shared__ float sA[NB];
    __shared__ float sred[NB];
    float thr  = fdecode(g_thrkey[mb]);
    float rmax = g_rowmax[mb * NB + i];
    float ll = g_ll [(mb * NB + i) * NB + j];
    float lr = g_lrn[(mb * NB + i) * NB + j];
    float a = __expf(ll - rmax - ((lr >= thr) ? 10000.0f : 0.0f)) * g_tc[mb * NB + j];
    sA[j] = a; sred[j] = a;
    __syncthreads();
    for (int off = 64; off; off >>= 1) { if (j < off) sred[j] += sred[j + off]; __syncthreads(); }
    if (j == 0) g_lownorm[mb * NB + i] = sred[0];
    if (j < DH) {
        float acc = 0.0f;
        for (int t = 0; t < NB; t++) acc += sA[t] * g_Vh[(mb * NB + t) * DH + j];
        g_lowout[(mb * NB + i) * DH + j] = acc;
    }
}

// ---------------- K8: final combine + head merge ----------------
__global__ void k_combine(const float* __restrict__ am, float* __restrict__ out) {
    int mb = blockIdx.y;
    int s  = blockIdx.x * 4 + (threadIdx.x >> 6);
    int e  = threadIdx.x & 63;
    int i = s >> 5, t = s & 31;
    float maskv = 1.0f + am[(mb & 1) * SEQ + s] / 10000.0f;
    float rm = g_rowmax[mb * NB + i];
    float mv = fdecode(g_maxblk[(mb * NB + i) * BS + t]);
    float lc = (rm - mv) * maskv;
    float locorr = __expf(fminf(lc, 0.0f));
    float hicorr = __expf(-fmaxf(lc, 0.0f));
    float hn = g_hinorm[mb * SEQ + s] * hicorr;
    float ln = g_lownorm[mb * NB + i] * locorr;
    float den = hn + ln + 1e-6f;
    float v = (g_hiout[((size_t)mb * SEQ + s) * DH + e] * hicorr
             + g_lowout[(mb * NB + i) * DH + e] * locorr) / den * maskv;
    int b = mb >> 4, h = mb & 15;
    out[((size_t)b * SEQ + s) * HDIM + h * DH + e] = v;
}

// ---------------- launch ----------------
extern "C" void kernel_launch(void* const* d_in, const int* in_sizes, int n_in,
                              void* d_out, int out_size) {
    const float* X  = (const float*)d_in[0];
    const float* am = (const float*)d_in[1];
    const float* wq = (const float*)d_in[2];
    const float* bq = (const float*)d_in[3];
    const float* wk = (const float*)d_in[4];
    const float* bk = (const float*)d_in[5];
    const float* wv = (const float*)d_in[6];
    const float* bv = (const float*)d_in[7];
    float* out = (float*)d_out;

    void *pQ, *pK, *pV, *pHi, *pHn, *pMx, *pCnt;
    cudaGetSymbolAddress(&pQ,  g_Q);
    cudaGetSymbolAddress(&pK,  g_K);
    cudaGetSymbolAddress(&pV,  g_V);
    cudaGetSymbolAddress(&pHi, g_hiout);
    cudaGetSymbolAddress(&pHn, g_hinorm);
    cudaGetSymbolAddress(&pMx, g_maxblk);
    cudaGetSymbolAddress(&pCnt, g_selcnt);

    cudaMemsetAsync(pHi, 0, sizeof(float) * (size_t)MB * SEQ * DH, 0);
    cudaMemsetAsync(pHn, 0, sizeof(float) * MB * SEQ, 0);
    cudaMemsetAsync(pMx, 0, sizeof(unsigned) * MB * NB * BS, 0);
    cudaMemsetAsync(pCnt, 0, sizeof(int) * MB, 0);

    dim3 gg(HDIM / 128, MROWS / 128);
    k_gemm<<<gg, 256>>>(X, wq, bq, am, (float*)pQ);
    k_gemm<<<gg, 256>>>(X, wk, bk, am, (float*)pK);
    k_gemm<<<gg, 256>>>(X, wv, bv, am, (float*)pV);

    k_stats<<<dim3(NB, MB), 64>>>(am);
    k_lowlogit<<<MB, 128>>>();
    k_topk<<<MB, 256>>>();
    k_himax<<<dim3(NSEL, MB), 256>>>();
    k_hiout<<<dim3(NSEL, MB), 256>>>(am);
    k_low<<<dim3(NB, MB), 128>>>();
    k_combine<<<dim3(SEQ / 4, MB), 256>>>(am, out);
}

// round 3
// speedup vs baseline: 1.1269x; 1.1269x over previous
#include <cuda_runtime.h>
#include <cuda_bf16.h>
#include <math.h>
#include <stdint.h>

// ---------------- problem constants ----------------
#define MB    32      // meta-batch = batch(2) * heads(16)
#define SEQ   4096
#define DH    64      // head dim
#define NB    128     // seq / 32 blocks
#define BS    32      // block size
#define NSEL  512     // NUM_BLOCKS
#define HDIM  1024
#define MROWS 8192    // batch * seq

// ---------------- scratch (device globals; no allocation allowed) ----------------
__device__ float    g_Q[(size_t)MB*SEQ*DH];
__device__ float    g_K[(size_t)MB*SEQ*DH];
__device__ float    g_V[(size_t)MB*SEQ*DH];
__device__ __nv_bfloat16 g_Xhi[(size_t)MROWS*HDIM];
__device__ __nv_bfloat16 g_Xlo[(size_t)MROWS*HDIM];
__device__ __nv_bfloat16 g_Whi[(size_t)3*HDIM*HDIM];
__device__ __nv_bfloat16 g_Wlo[(size_t)3*HDIM*HDIM];
__device__ float    g_Qh[MB*NB*DH];
__device__ float    g_Kh[MB*NB*DH];
__device__ float    g_Vh[MB*NB*DH];
__device__ float    g_tc[MB*NB];
__device__ float    g_ll[MB*NB*NB];      // masked low-res logits
__device__ float    g_lrn[MB*NB*NB];     // lrn (logit - rowmax + band)
__device__ float    g_rowmax[MB*NB];
__device__ unsigned g_thrkey[MB];
__device__ int      g_selidx[MB*NSEL];
__device__ int      g_selcnt[MB];
__device__ unsigned g_maxblk[MB*NB*BS];  // ordered-uint encoded scatter-max
__device__ float    g_hiout[(size_t)MB*SEQ*DH];
__device__ float    g_hinorm[MB*SEQ];
__device__ float    g_lowout[MB*NB*DH];
__device__ float    g_lownorm[MB*NB];

// order-preserving float <-> uint mapping
__device__ __forceinline__ unsigned fkey(float f) {
    unsigned u = __float_as_uint(f);
    return (u & 0x80000000u) ? ~u : (u | 0x80000000u);
}
__device__ __forceinline__ float fdecode(unsigned k) {
    unsigned u = (k & 0x80000000u) ? (k & 0x7FFFFFFFu) : ~k;
    return __uint_as_float(u);
}

__device__ __forceinline__ uint32_t smem_u32(const void* p) {
    uint32_t a;
    asm("{ .reg .u64 t; cvta.to.shared.u64 t, %1; cvt.u32.u64 %0, t; }" : "=r"(a) : "l"(p));
    return a;
}

#define LDSM4(r, a) \
    asm volatile("ldmatrix.sync.aligned.m8n8.x4.shared.b16 {%0,%1,%2,%3}, [%4];" \
        : "=r"((r)[0]), "=r"((r)[1]), "=r"((r)[2]), "=r"((r)[3]) : "r"(a))

#define MMA16816(d, a, b0, b1) \
    asm volatile("mma.sync.aligned.m16n8k16.row.col.f32.bf16.bf16.f32 " \
        "{%0,%1,%2,%3}, {%4,%5,%6,%7}, {%8,%9}, {%0,%1,%2,%3};" \
        : "+f"((d)[0]), "+f"((d)[1]), "+f"((d)[2]), "+f"((d)[3]) \
        : "r"((a)[0]), "r"((a)[1]), "r"((a)[2]), "r"((a)[3]), "r"(b0), "r"(b1))

#define CP16(saddr, gptr) \
    asm volatile("cp.async.cg.shared.global [%0], [%1], 16;" :: "r"(saddr), "l"(gptr) : "memory")
#define CP_COMMIT() asm volatile("cp.async.commit_group;" ::: "memory")
#define CP_WAIT1()  asm volatile("cp.async.wait_group 1;" ::: "memory")
#define CP_WAIT0()  asm volatile("cp.async.wait_group 0;" ::: "memory")

// ---------------- K0: fp32 -> bf16 hi/lo split ----------------
__global__ void k_split(const float4* __restrict__ src, __nv_bfloat162* __restrict__ hi,
                        __nv_bfloat162* __restrict__ lo, int n4) {
    int i = blockIdx.x * blockDim.x + threadIdx.x;
    if (i >= n4) return;
    float4 v = src[i];
    __nv_bfloat16 h0 = __float2bfloat16(v.x), h1 = __float2bfloat16(v.y);
    __nv_bfloat16 h2 = __float2bfloat16(v.z), h3 = __float2bfloat16(v.w);
    __nv_bfloat16 l0 = __float2bfloat16(v.x - __bfloat162float(h0));
    __nv_bfloat16 l1 = __float2bfloat16(v.y - __bfloat162float(h1));
    __nv_bfloat16 l2 = __float2bfloat16(v.z - __bfloat162float(h2));
    __nv_bfloat16 l3 = __float2bfloat16(v.w - __bfloat162float(h3));
    hi[2*i]   = __halves2bfloat162(h0, h1);
    hi[2*i+1] = __halves2bfloat162(h2, h3);
    lo[2*i]   = __halves2bfloat162(l0, l1);
    lo[2*i+1] = __halves2bfloat162(l2, l3);
}

// ---------------- K1: bf16 mma.sync QKV projection GEMM ----------------
// CTA 128x128, 4 warps (2x2), warp tile 64x64. K-chunk 32, 2-stage cp.async pipeline.
// 2-term split: acc = Ah*Bh + Al*Bh + Ah*Bl. Epilogue: +bias, *mask, head-split scatter.
#define KCH      32
#define NCHUNK   (HDIM / KCH)       // 32
#define RSTRIDE  80                 // bytes per smem row (32 bf16 data + 8 pad)
#define TILE_B   10240              // 128 rows * 80 B
#define STAGE_B  (4 * TILE_B)       // Ah, Al, Bh, Bl
#define GEMM_SMEM (2 * STAGE_B)     // 81920

__global__ __launch_bounds__(128) void k_gemm_mma(
    const float* __restrict__ am, const float* __restrict__ bq,
    const float* __restrict__ bk, const float* __restrict__ bv)
{
    extern __shared__ char sm_[];
    uint32_t sb = smem_u32(sm_);
    int tid = threadIdx.x, lid = tid & 31, wid = tid >> 5;
    int wm = wid >> 1, wn = wid & 1;
    int proj = blockIdx.z;
    int n0 = blockIdx.x * 128, m0 = blockIdx.y * 128;

    const __nv_bfloat16* Ahp = g_Xhi;
    const __nv_bfloat16* Alp = g_Xlo;
    const __nv_bfloat16* Bhp = g_Whi + (size_t)proj * HDIM * HDIM;
    const __nv_bfloat16* Blp = g_Wlo + (size_t)proj * HDIM * HDIM;
    const float* bias = (proj == 0) ? bq : ((proj == 1) ? bk : bv);
    float* out = (proj == 0) ? g_Q : ((proj == 1) ? g_K : g_V);

    float acc[4][8][4];
    #pragma unroll
    for (int mt = 0; mt < 4; mt++)
        #pragma unroll
        for (int nt = 0; nt < 8; nt++)
            #pragma unroll
            for (int r = 0; r < 4; r++) acc[mt][nt][r] = 0.0f;

    // per-thread load units: 4 per tile; unit -> row = u>>2, kc = u&3 (16B each)
    int u0r[4], u0k[4];
    #pragma unroll
    for (int j = 0; j < 4; j++) { int u = tid + j * 128; u0r[j] = u >> 2; u0k[j] = u & 3; }

    #define LOAD_CHUNK(ch, s) do {                                              \
        uint32_t st_ = sb + (s) * STAGE_B;                                      \
        int gk_ = (ch) * KCH;                                                   \
        _Pragma("unroll")                                                       \
        for (int j = 0; j < 4; j++) {                                           \
            int row = u0r[j], kc = u0k[j];                                      \
            uint32_t so = row * RSTRIDE + kc * 16;                              \
            size_t ga = (size_t)(m0 + row) * HDIM + gk_ + kc * 8;               \
            size_t gb = (size_t)(n0 + row) * HDIM + gk_ + kc * 8;               \
            CP16(st_ + 0 * TILE_B + so, Ahp + ga);                              \
            CP16(st_ + 1 * TILE_B + so, Alp + ga);                              \
            CP16(st_ + 2 * TILE_B + so, Bhp + gb);                              \
            CP16(st_ + 3 * TILE_B + so, Blp + gb);                              \
        }                                                                       \
        CP_COMMIT();                                                            \
    } while (0)

    LOAD_CHUNK(0, 0);
    LOAD_CHUNK(1, 1);

    int g = lid >> 3, lr = lid & 7;
    // A ldmatrix lane addr offsets: rows R+lr (+8 if g odd), k-bytes +16 if g>=2
    int a_roff = lr + (g & 1) * 8;
    int a_koff = (g >> 1) * 16;
    // B ldmatrix lane addr offsets: rows n+lr (+8 if g>=2), k-bytes +16 if g odd
    int b_roff = lr + (g >> 1) * 8;
    int b_koff = (g & 1) * 16;

    for (int ch = 0; ch < NCHUNK; ch++) {
        int s = ch & 1;
        if (ch < NCHUNK - 1) { CP_WAIT1(); } else { CP_WAIT0(); }
        __syncthreads();
        uint32_t st = sb + s * STAGE_B;
        #pragma unroll
        for (int ks = 0; ks < 2; ks++) {
            uint32_t koff = ks * 32;
            uint32_t ah[4][4], al[4][4], bb[4][4];
            // load A hi & lo fragments (4 m16 tiles each)
            #pragma unroll
            for (int mt = 0; mt < 4; mt++) {
                uint32_t addr = st + (wm * 64 + mt * 16 + a_roff) * RSTRIDE + koff + a_koff;
                LDSM4(ah[mt], addr + 0 * TILE_B);
                LDSM4(al[mt], addr + 1 * TILE_B);
            }
            // B hi fragments: 4 ldmatrix.x4, each covers n16 x k16 (two b-frags)
            #pragma unroll
            for (int np = 0; np < 4; np++) {
                uint32_t addr = st + 2 * TILE_B + (wn * 64 + np * 16 + b_roff) * RSTRIDE + koff + b_koff;
                LDSM4(bb[np], addr);
            }
            #pragma unroll
            for (int mt = 0; mt < 4; mt++)
                #pragma unroll
                for (int np = 0; np < 4; np++) {
                    MMA16816(acc[mt][2*np+0], ah[mt], bb[np][0], bb[np][1]);
                    MMA16816(acc[mt][2*np+1], ah[mt], bb[np][2], bb[np][3]);
                }
            #pragma unroll
            for (int mt = 0; mt < 4; mt++)
                #pragma unroll
                for (int np = 0; np < 4; np++) {
                    MMA16816(acc[mt][2*np+0], al[mt], bb[np][0], bb[np][1]);
                    MMA16816(acc[mt][2*np+1], al[mt], bb[np][2], bb[np][3]);
                }
            // B lo fragments (reuse bb), combine with A hi
            #pragma unroll
            for (int np = 0; np < 4; np++) {
                uint32_t addr = st + 3 * TILE_B + (wn * 64 + np * 16 + b_roff) * RSTRIDE + koff + b_koff;
                LDSM4(bb[np], addr);
            }
            #pragma unroll
            for (int mt = 0; mt < 4; mt++)
                #pragma unroll
                for (int np = 0; np < 4; np++) {
                    MMA16816(acc[mt][2*np+0], ah[mt], bb[np][0], bb[np][1]);
                    MMA16816(acc[mt][2*np+1], ah[mt], bb[np][2], bb[np][3]);
                }
        }
        __syncthreads();
        if (ch + 2 < NCHUNK) LOAD_CHUNK(ch + 2, s);
    }

    // ---- epilogue ----
    int r4 = lid >> 2, c2 = (lid & 3) * 2;
    #pragma unroll
    for (int mt = 0; mt < 4; mt++) {
        #pragma unroll
        for (int half = 0; half < 2; half++) {
            int m = m0 + wm * 64 + mt * 16 + r4 + half * 8;
            int b_ = m >> 12, sidx = m & 4095;
            #pragma unroll
            for (int nt = 0; nt < 8; nt++) {
                int n = n0 + wn * 64 + nt * 8 + c2;
                int h = n >> 6, e = n & 63;
                float maskv = 1.0f + __ldg(am + (h & 1) * SEQ + sidx) * 1e-4f;
                int mbi = b_ * 16 + h;
                float2 v;
                v.x = (acc[mt][nt][half*2+0] + __ldg(bias + n))     * maskv;
                v.y = (acc[mt][nt][half*2+1] + __ldg(bias + n + 1)) * maskv;
                *(float2*)(out + ((size_t)mbi * SEQ + sidx) * DH + e) = v;
            }
        }
    }
    #undef LOAD_CHUNK
}

// ---------------- K2: block means + token counts ----------------
__global__ void k_stats(const float* __restrict__ am) {
    int mb = blockIdx.y, i = blockIdx.x, e = threadIdx.x; // 64 threads
    float tc = 0.0f;
    int amb = (mb & 1) * SEQ + i * BS;
    for (int t = 0; t < BS; t++) tc += 1.0f + am[amb + t] / 10000.0f;
    float den = tc + 1e-6f;
    const float* Qp = g_Q + ((size_t)mb * SEQ + i * BS) * DH + e;
    const float* Kp = g_K + ((size_t)mb * SEQ + i * BS) * DH + e;
    const float* Vp = g_V + ((size_t)mb * SEQ + i * BS) * DH + e;
    float sq = 0, sk = 0, sv = 0;
    for (int t = 0; t < BS; t++) { sq += Qp[t*DH]; sk += Kp[t*DH]; sv += Vp[t*DH]; }
    int o = (mb * NB + i) * DH + e;
    g_Qh[o] = sq / den; g_Kh[o] = sk / den; g_Vh[o] = sv / den;
    if (e == 0) g_tc[mb * NB + i] = tc;
}

// ---------------- K3: low-res logits, row max, lrn (band added) ----------------
__global__ __launch_bounds__(128) void k_lowlogit() {
    int mb = blockIdx.x, i = threadIdx.x;
    __shared__ float sK[NB * DH];   // 32KB
    __shared__ float sTc[NB];
    for (int t = i; t < NB * DH; t += 128) sK[t] = g_Kh[mb * NB * DH + t];
    if (i < NB) sTc[i] = g_tc[mb * NB + i];
    __syncthreads();

    float qr[DH];
    #pragma unroll
    for (int k = 0; k < DH; k++) qr[k] = g_Qh[(mb * NB + i) * DH + k];

    float row[NB];
    float rmax = -INFINITY;
    for (int j = 0; j < NB; j++) {
        float d = 0.0f;
        #pragma unroll
        for (int k = 0; k < DH; k++) d += qr[k] * sK[j * DH + k];
        d *= 0.125f;                 // 1/sqrt(64)
        row[j] = d;
        rmax = fmaxf(rmax, d);       // max BEFORE mask subtraction (matches reference)
    }
    g_rowmax[mb * NB + i] = rmax;
    float tci = sTc[i];
    for (int j = 0; j < NB; j++) {
        float ll = row[j];
        if (tci * sTc[j] < 0.5f) ll -= 10000.0f;
        float lr = ll - rmax;
        int dd = i - j; if (dd < 0) dd = -dd;
        if (dd <= 1) lr += 5000.0f;  // DIAG_N=3 band
        g_ll [(mb * NB + i) * NB + j] = ll;
        g_lrn[(mb * NB + i) * NB + j] = lr;
    }
}

// ---------------- K4: top-512 via smem-cached bitwise binary search ----------------
__global__ __launch_bounds__(256) void k_topk() {
    extern __shared__ unsigned skey[];   // 16384 keys = 64KB
    int mb = blockIdx.x, tid = threadIdx.x;
    const float* base = g_lrn + mb * NB * NB;
    __shared__ unsigned sred[256];
    for (int idx = tid; idx < NB * NB; idx += 256) skey[idx] = fkey(base[idx]);
    __syncthreads();
    unsigned lo = 0, hi = 0xFFFFFFFFu;
    while (lo < hi) {
        unsigned mid = (unsigned)(((unsigned long long)lo + (unsigned long long)hi + 1ull) >> 1);
        unsigned c = 0;
        for (int idx = tid; idx < NB * NB; idx += 256) c += (skey[idx] >= mid) ? 1u : 0u;
        sred[tid] = c; __syncthreads();
        for (int off = 128; off; off >>= 1) { if (tid < off) sred[tid] += sred[tid + off]; __syncthreads(); }
        unsigned cnt = sred[0]; __syncthreads();
        if (cnt >= NSEL) lo = mid; else hi = mid - 1;
    }
    if (tid == 0) g_thrkey[mb] = lo;
    for (int idx = tid; idx < NB * NB; idx += 256) {
        if (skey[idx] >= lo) {
            int p = atomicAdd(&g_selcnt[mb], 1);
            if (p < NSEL) g_selidx[mb * NSEL + p] = idx;
        }
    }
}

// ---------------- K5: hi-branch pass 1 — per-query-row scatter max over selected blocks ----------------
__global__ __launch_bounds__(256) void k_himax() {
    int mb = blockIdx.y, p = blockIdx.x, tid = threadIdx.x;
    int cnt = g_selcnt[mb]; if (cnt > NSEL) cnt = NSEL;
    if (p >= cnt) return;
    int idx = g_selidx[mb * NSEL + p];
    int qb = idx >> 7, kb = idx & 127;
    __shared__ float sQ[BS * 65], sK[BS * 65], sL[BS * 33];
    const float* Qg = g_Q + ((size_t)mb * SEQ + qb * BS) * DH;
    const float* Kg = g_K + ((size_t)mb * SEQ + kb * BS) * DH;
    for (int t = tid; t < BS * DH; t += 256) {
        int r = t >> 6, cc = t & 63;
        sQ[r * 65 + cc] = Qg[t];
        sK[r * 65 + cc] = Kg[t];
    }
    __syncthreads();
    for (int l = tid; l < BS * BS; l += 256) {
        int q = l >> 5, k = l & 31;
        float d = 0.0f;
        #pragma unroll
        for (int e = 0; e < DH; e++) d += sK[k * 65 + e] * sQ[q * 65 + e];
        sL[k * 33 + q] = d * 0.125f;
    }
    __syncthreads();
    if (tid < BS) {
        int q = tid; float m = -INFINITY;
        for (int k = 0; k < BS; k++) m = fmaxf(m, sL[k * 33 + q]); // unmasked max (matches ref)
        atomicMax(&g_maxblk[(mb * NB + qb) * BS + q], fkey(m));
    }
}

// ---------------- K6: hi-branch pass 2 — exp + A@V scatter-add + normalizer ----------------
__global__ __launch_bounds__(256) void k_hiout(const float* __restrict__ am) {
    int mb = blockIdx.y, p = blockIdx.x, tid = threadIdx.x;
    int cnt = g_selcnt[mb]; if (cnt > NSEL) cnt = NSEL;
    if (p >= cnt) return;
    int idx = g_selidx[mb * NSEL + p];
    int qb = idx >> 7, kb = idx & 127;
    __shared__ float sQ[BS * 65], sK[BS * 65], sV[BS * 68], sA[BS * 33], sMq[BS], sMk[BS];
    const float* Qg = g_Q + ((size_t)mb * SEQ + qb * BS) * DH;
    const float* Kg = g_K + ((size_t)mb * SEQ + kb * BS) * DH;
    const float* Vg = g_V + ((size_t)mb * SEQ + kb * BS) * DH;
    for (int t = tid; t < BS * DH; t += 256) {
        int r = t >> 6, cc = t & 63;
        sQ[r * 65 + cc] = Qg[t];
        sK[r * 65 + cc] = Kg[t];
        sV[r * 68 + cc] = Vg[t];
    }
    if (tid < BS) {
        sMq[tid] = fdecode(g_maxblk[(mb * NB + qb) * BS + tid]);
        sMk[tid] = 1.0f + am[(mb & 1) * SEQ + kb * BS + tid] / 10000.0f;
    }
    __syncthreads();
    for (int l = tid; l < BS * BS; l += 256) {
        int q = l >> 5, k = l & 31;
        float d = 0.0f;
        #pragma unroll
        for (int e = 0; e < DH; e++) d += sK[k * 65 + e] * sQ[q * 65 + e];
        d = d * 0.125f - sMq[q] - 10000.0f * (1.0f - sMk[k]);
        sA[k * 33 + q] = __expf(d);
    }
    __syncthreads();
    int q = tid >> 3, g = tid & 7, e0 = g * 8;
    float acc[8] = {0,0,0,0,0,0,0,0};
    float nsum = 0.0f;
    for (int k = 0; k < BS; k++) {
        float a = sA[k * 33 + q];
        nsum += a;
        #pragma unroll
        for (int j = 0; j < 8; j++) acc[j] += a * sV[k * 68 + e0 + j];
    }
    float* dst = g_hiout + ((size_t)mb * SEQ + qb * BS + q) * DH + e0;
    #pragma unroll
    for (int j = 0; j < 8; j++) atomicAdd(dst + j, acc[j]);
    if (g == 0) atomicAdd(&g_hinorm[mb * SEQ + qb * BS + q], nsum);
}

// ---------------- K7: low-res branch (selected blocks suppressed) ----------------
__global__ __launch_bounds__(128) void k_low() {
    int mb = blockIdx.y, i = blockIdx.x, j = threadIdx.x;
    __shared__ float sA[NB];
    __shared__ float sred[NB];
    float thr  = fdecode(g_thrkey[mb]);
    float rmax = g_rowmax[mb * NB + i];
    float ll = g_ll [(mb * NB + i) * NB + j];
    float lr = g_lrn[(mb * NB + i) * NB + j];
    float a = __expf(ll - rmax - ((lr >= thr) ? 10000.0f : 0.0f)) * g_tc[mb * NB + j];
    sA[j] = a; sred[j] = a;
    __syncthreads();
    for (int off = 64; off; off >>= 1) { if (j < off) sred[j] += sred[j + off]; __syncthreads(); }
    if (j == 0) g_lownorm[mb * NB + i] = sred[0];
    if (j < DH) {
        float acc = 0.0f;
        for (int t = 0; t < NB; t++) acc += sA[t] * g_Vh[(mb * NB + t) * DH + j];
        g_lowout[(mb * NB + i) * DH + j] = acc;
    }
}

// ---------------- K8: final combine + head merge ----------------
__global__ void k_combine(const float* __restrict__ am, float* __restrict__ out) {
    int mb = blockIdx.y;
    int s  = blockIdx.x * 4 + (threadIdx.x >> 6);
    int e  = threadIdx.x & 63;
    int i = s >> 5, t = s & 31;
    float maskv = 1.0f + am[(mb & 1) * SEQ + s] / 10000.0f;
    float rm = g_rowmax[mb * NB + i];
    float mv = fdecode(g_maxblk[(mb * NB + i) * BS + t]);
    float lc = (rm - mv) * maskv;
    float locorr = __expf(fminf(lc, 0.0f));
    float hicorr = __expf(-fmaxf(lc, 0.0f));
    float hn = g_hinorm[mb * SEQ + s] * hicorr;
    float ln = g_lownorm[mb * NB + i] * locorr;
    float den = hn + ln + 1e-6f;
    float v = (g_hiout[((size_t)mb * SEQ + s) * DH + e] * hicorr
             + g_lowout[(mb * NB + i) * DH + e] * locorr) / den * maskv;
    int b = mb >> 4, h = mb & 15;
    out[((size_t)b * SEQ + s) * HDIM + h * DH + e] = v;
}

// ---------------- launch ----------------
extern "C" void kernel_launch(void* const* d_in, const int* in_sizes, int n_in,
                              void* d_out, int out_size) {
    const float* X  = (const float*)d_in[0];
    const float* am = (const float*)d_in[1];
    const float* wq = (const float*)d_in[2];
    const float* bq = (const float*)d_in[3];
    const float* wk = (const float*)d_in[4];
    const float* bk = (const float*)d_in[5];
    const float* wv = (const float*)d_in[6];
    const float* bv = (const float*)d_in[7];
    float* out = (float*)d_out;

    void *pHi, *pHn, *pMx, *pCnt, *pXhi, *pXlo, *pWhi, *pWlo;
    cudaGetSymbolAddress(&pHi,  g_hiout);
    cudaGetSymbolAddress(&pHn,  g_hinorm);
    cudaGetSymbolAddress(&pMx,  g_maxblk);
    cudaGetSymbolAddress(&pCnt, g_selcnt);
    cudaGetSymbolAddress(&pXhi, g_Xhi);
    cudaGetSymbolAddress(&pXlo, g_Xlo);
    cudaGetSymbolAddress(&pWhi, g_Whi);
    cudaGetSymbolAddress(&pWlo, g_Wlo);

    cudaFuncSetAttribute(k_gemm_mma, cudaFuncAttributeMaxDynamicSharedMemorySize, GEMM_SMEM);
    cudaFuncSetAttribute(k_topk, cudaFuncAttributeMaxDynamicSharedMemorySize, 65536);

    cudaMemsetAsync(pHi, 0, sizeof(float) * (size_t)MB * SEQ * DH, 0);
    cudaMemsetAsync(pHn, 0, sizeof(float) * MB * SEQ, 0);
    cudaMemsetAsync(pMx, 0, sizeof(unsigned) * MB * NB * BS, 0);
    cudaMemsetAsync(pCnt, 0, sizeof(int) * MB, 0);

    // split fp32 -> bf16 hi/lo
    int nx4 = MROWS * HDIM / 4;       // 2097152
    int nw4 = HDIM * HDIM / 4;        // 262144
    k_split<<<(nx4 + 255) / 256, 256>>>((const float4*)X,  (__nv_bfloat162*)pXhi, (__nv_bfloat162*)pXlo, nx4);
    k_split<<<(nw4 + 255) / 256, 256>>>((const float4*)wq, (__nv_bfloat162*)pWhi, (__nv_bfloat162*)pWlo, nw4);
    k_split<<<(nw4 + 255) / 256, 256>>>((const float4*)wk,
        (__nv_bfloat162*)((char*)pWhi + (size_t)HDIM*HDIM*2), (__nv_bfloat162*)((char*)pWlo + (size_t)HDIM*HDIM*2), nw4);
    k_split<<<(nw4 + 255) / 256, 256>>>((const float4*)wv,
        (__nv_bfloat162*)((char*)pWhi + (size_t)2*HDIM*HDIM*2), (__nv_bfloat162*)((char*)pWlo + (size_t)2*HDIM*HDIM*2), nw4);

    k_gemm_mma<<<dim3(HDIM / 128, MROWS / 128, 3), 128, GEMM_SMEM>>>(am, bq, bk, bv);

    k_stats<<<dim3(NB, MB), 64>>>(am);
    k_lowlogit<<<MB, 128>>>();
    k_topk<<<MB, 256, 65536>>>();
    k_himax<<<dim3(NSEL, MB), 256>>>();
    k_hiout<<<dim3(NSEL, MB), 256>>>(am);
    k_low<<<dim3(NB, MB), 128>>>();
    k_combine<<<dim3(SEQ / 4, MB), 256>>>(am, out);
}

// round 4
// speedup vs baseline: 1.6857x; 1.4959x over previous
#include <cuda_runtime.h>
#include <cuda_bf16.h>
#include <math.h>
#include <stdint.h>

// ---------------- problem constants ----------------
#define MB    32      // meta-batch = batch(2) * heads(16)
#define SEQ   4096
#define DH    64      // head dim
#define NB    128     // seq / 32 blocks
#define BS    32      // block size
#define NSEL  512     // NUM_BLOCKS
#define HDIM  1024
#define MROWS 8192    // batch * seq

// ---------------- scratch (device globals; no allocation allowed) ----------------
__device__ float    g_Q[(size_t)MB*SEQ*DH];
__device__ float    g_K[(size_t)MB*SEQ*DH];
__device__ float    g_V[(size_t)MB*SEQ*DH];
__device__ __nv_bfloat16 g_Xhi[(size_t)MROWS*HDIM];
__device__ __nv_bfloat16 g_Xlo[(size_t)MROWS*HDIM];
__device__ __nv_bfloat16 g_Whi[(size_t)3*HDIM*HDIM];
__device__ __nv_bfloat16 g_Wlo[(size_t)3*HDIM*HDIM];
__device__ float    g_Qh[MB*NB*DH];
__device__ float    g_Kh[MB*NB*DH];
__device__ float    g_Vh[MB*NB*DH];
__device__ float    g_tc[MB*NB];
__device__ float    g_ll[MB*NB*NB];      // masked low-res logits
__device__ float    g_lrn[MB*NB*NB];     // lrn (logit - rowmax + band)
__device__ float    g_rowmax[MB*NB];
__device__ unsigned g_thrkey[MB];
__device__ int      g_qcnt[MB*NB];       // selected kb count per (mb, qb)
__device__ int      g_qlist[MB*NB*NB];   // kb list per (mb, qb)
__device__ float    g_maxblkf[MB*NB*BS]; // per-query-row max over selected blocks
__device__ float    g_hiout[(size_t)MB*SEQ*DH];
__device__ float    g_hinorm[MB*SEQ];
__device__ float    g_lowout[MB*NB*DH];
__device__ float    g_lownorm[MB*NB];

// order-preserving float <-> uint mapping
__device__ __forceinline__ unsigned fkey(float f) {
    unsigned u = __float_as_uint(f);
    return (u & 0x80000000u) ? ~u : (u | 0x80000000u);
}
__device__ __forceinline__ float fdecode(unsigned k) {
    unsigned u = (k & 0x80000000u) ? (k & 0x7FFFFFFFu) : ~k;
    return __uint_as_float(u);
}

__device__ __forceinline__ uint32_t smem_u32(const void* p) {
    uint32_t a;
    asm("{ .reg .u64 t; cvta.to.shared.u64 t, %1; cvt.u32.u64 %0, t; }" : "=r"(a) : "l"(p));
    return a;
}

#define LDSM4(r, a) \
    asm volatile("ldmatrix.sync.aligned.m8n8.x4.shared.b16 {%0,%1,%2,%3}, [%4];" \
        : "=r"((r)[0]), "=r"((r)[1]), "=r"((r)[2]), "=r"((r)[3]) : "r"(a))

#define MMA16816(d, a, b0, b1) \
    asm volatile("mma.sync.aligned.m16n8k16.row.col.f32.bf16.bf16.f32 " \
        "{%0,%1,%2,%3}, {%4,%5,%6,%7}, {%8,%9}, {%0,%1,%2,%3};" \
        : "+f"((d)[0]), "+f"((d)[1]), "+f"((d)[2]), "+f"((d)[3]) \
        : "r"((a)[0]), "r"((a)[1]), "r"((a)[2]), "r"((a)[3]), "r"(b0), "r"(b1))

#define CP16(saddr, gptr) \
    asm volatile("cp.async.cg.shared.global [%0], [%1], 16;" :: "r"(saddr), "l"(gptr) : "memory")
#define CP_COMMIT() asm volatile("cp.async.commit_group;" ::: "memory")
#define CP_WAIT1()  asm volatile("cp.async.wait_group 1;" ::: "memory")
#define CP_WAIT0()  asm volatile("cp.async.wait_group 0;" ::: "memory")

// ---------------- K0: fp32 -> bf16 hi/lo split ----------------
__global__ void k_split(const float4* __restrict__ src, __nv_bfloat162* __restrict__ hi,
                        __nv_bfloat162* __restrict__ lo, int n4) {
    int i = blockIdx.x * blockDim.x + threadIdx.x;
    if (i >= n4) return;
    float4 v = src[i];
    __nv_bfloat16 h0 = __float2bfloat16(v.x), h1 = __float2bfloat16(v.y);
    __nv_bfloat16 h2 = __float2bfloat16(v.z), h3 = __float2bfloat16(v.w);
    __nv_bfloat16 l0 = __float2bfloat16(v.x - __bfloat162float(h0));
    __nv_bfloat16 l1 = __float2bfloat16(v.y - __bfloat162float(h1));
    __nv_bfloat16 l2 = __float2bfloat16(v.z - __bfloat162float(h2));
    __nv_bfloat16 l3 = __float2bfloat16(v.w - __bfloat162float(h3));
    hi[2*i]   = __halves2bfloat162(h0, h1);
    hi[2*i+1] = __halves2bfloat162(h2, h3);
    lo[2*i]   = __halves2bfloat162(l0, l1);
    lo[2*i+1] = __halves2bfloat162(l2, l3);
}

// ---------------- K0b: zero small counters ----------------
__global__ void k_zero() {
    int i = blockIdx.x * blockDim.x + threadIdx.x;
    if (i < MB * NB) g_qcnt[i] = 0;
}

// ---------------- K1: bf16 mma.sync QKV projection GEMM ----------------
// CTA 128x128, 8 warps (2x4), warp tile 64x32. K-chunk 32, 2-stage cp.async pipeline.
// 2-term split: acc = Ah*Bh + Ah*Bl + Al*Bh.
#define KCH      32
#define RSTRIDE  80                 // bytes per smem row (64B data + 16 pad)
#define TILE_B   10240              // 128 rows * 80 B
#define STAGE_B  (4 * TILE_B)       // Ah, Al, Bh, Bl
#define NCHUNK   (HDIM / KCH)       // 32
#define GEMM_SMEM (2 * STAGE_B)     // 81920

__global__ __launch_bounds__(256, 1) void k_gemm_mma(
    const float* __restrict__ am, const float* __restrict__ bq,
    const float* __restrict__ bk, const float* __restrict__ bv)
{
    extern __shared__ char sm_[];
    uint32_t sb = smem_u32(sm_);
    int tid = threadIdx.x, lid = tid & 31, wid = tid >> 5;
    int wm = wid >> 2, wn = wid & 3;
    int proj = blockIdx.z;
    int n0 = blockIdx.x * 128, m0 = blockIdx.y * 128;

    const __nv_bfloat16* Ahp = g_Xhi;
    const __nv_bfloat16* Alp = g_Xlo;
    const __nv_bfloat16* Bhp = g_Whi + (size_t)proj * HDIM * HDIM;
    const __nv_bfloat16* Blp = g_Wlo + (size_t)proj * HDIM * HDIM;
    const float* bias = (proj == 0) ? bq : ((proj == 1) ? bk : bv);
    float* out = (proj == 0) ? g_Q : ((proj == 1) ? g_K : g_V);

    float acc[4][4][4];
    #pragma unroll
    for (int mt = 0; mt < 4; mt++)
        #pragma unroll
        for (int nt = 0; nt < 4; nt++)
            #pragma unroll
            for (int r = 0; r < 4; r++) acc[mt][nt][r] = 0.0f;

    // per-thread load units: 512 cp16 per tile, 2 per thread
    int u0r[2], u0k[2];
    #pragma unroll
    for (int j = 0; j < 2; j++) { int u = tid + j * 256; u0r[j] = u >> 2; u0k[j] = u & 3; }

    #define LOAD_CHUNK(ch, s) do {                                              \
        uint32_t st_ = sb + (s) * STAGE_B;                                      \
        int gk_ = (ch) * KCH;                                                   \
        _Pragma("unroll")                                                       \
        for (int j = 0; j < 2; j++) {                                           \
            int row = u0r[j], kc = u0k[j];                                      \
            uint32_t so = row * RSTRIDE + kc * 16;                              \
            size_t ga = (size_t)(m0 + row) * HDIM + gk_ + kc * 8;               \
            size_t gb = (size_t)(n0 + row) * HDIM + gk_ + kc * 8;               \
            CP16(st_ + 0 * TILE_B + so, Ahp + ga);                              \
            CP16(st_ + 1 * TILE_B + so, Alp + ga);                              \
            CP16(st_ + 2 * TILE_B + so, Bhp + gb);                              \
            CP16(st_ + 3 * TILE_B + so, Blp + gb);                              \
        }                                                                       \
        CP_COMMIT();                                                            \
    } while (0)

    LOAD_CHUNK(0, 0);
    LOAD_CHUNK(1, 1);

    int g = lid >> 3, lr = lid & 7;
    int a_roff = lr + (g & 1) * 8;
    int a_koff = (g >> 1) * 16;
    int b_roff = lr + (g >> 1) * 8;
    int b_koff = (g & 1) * 16;

    for (int ch = 0; ch < NCHUNK; ch++) {
        int s = ch & 1;
        if (ch < NCHUNK - 1) { CP_WAIT1(); } else { CP_WAIT0(); }
        __syncthreads();
        uint32_t st = sb + s * STAGE_B;
        #pragma unroll
        for (int ks = 0; ks < 2; ks++) {
            uint32_t koff = ks * 32;
            uint32_t ah[4][4], al[4][4], bh[2][4], bl[2][4];
            #pragma unroll
            for (int mt = 0; mt < 4; mt++) {
                uint32_t addr = st + (wm * 64 + mt * 16 + a_roff) * RSTRIDE + koff + a_koff;
                LDSM4(ah[mt], addr);
            }
            #pragma unroll
            for (int np = 0; np < 2; np++) {
                uint32_t addr = st + 2 * TILE_B + (wn * 32 + np * 16 + b_roff) * RSTRIDE + koff + b_koff;
                LDSM4(bh[np], addr);
            }
            #pragma unroll
            for (int mt = 0; mt < 4; mt++)
                #pragma unroll
                for (int np = 0; np < 2; np++) {
                    MMA16816(acc[mt][2*np+0], ah[mt], bh[np][0], bh[np][1]);
                    MMA16816(acc[mt][2*np+1], ah[mt], bh[np][2], bh[np][3]);
                }
            #pragma unroll
            for (int np = 0; np < 2; np++) {
                uint32_t addr = st + 3 * TILE_B + (wn * 32 + np * 16 + b_roff) * RSTRIDE + koff + b_koff;
                LDSM4(bl[np], addr);
            }
            #pragma unroll
            for (int mt = 0; mt < 4; mt++)
                #pragma unroll
                for (int np = 0; np < 2; np++) {
                    MMA16816(acc[mt][2*np+0], ah[mt], bl[np][0], bl[np][1]);
                    MMA16816(acc[mt][2*np+1], ah[mt], bl[np][2], bl[np][3]);
                }
            #pragma unroll
            for (int mt = 0; mt < 4; mt++) {
                uint32_t addr = st + TILE_B + (wm * 64 + mt * 16 + a_roff) * RSTRIDE + koff + a_koff;
                LDSM4(al[mt], addr);
            }
            #pragma unroll
            for (int mt = 0; mt < 4; mt++)
                #pragma unroll
                for (int np = 0; np < 2; np++) {
                    MMA16816(acc[mt][2*np+0], al[mt], bh[np][0], bh[np][1]);
                    MMA16816(acc[mt][2*np+1], al[mt], bh[np][2], bh[np][3]);
                }
        }
        __syncthreads();
        if (ch + 2 < NCHUNK) LOAD_CHUNK(ch + 2, s);
    }

    // ---- epilogue: +bias, *mask, head-split scatter ----
    int r4 = lid >> 2, c2 = (lid & 3) * 2;
    #pragma unroll
    for (int mt = 0; mt < 4; mt++) {
        #pragma unroll
        for (int half = 0; half < 2; half++) {
            int m = m0 + wm * 64 + mt * 16 + r4 + half * 8;
            int b_ = m >> 12, sidx = m & 4095;
            #pragma unroll
            for (int nt = 0; nt < 4; nt++) {
                int n = n0 + wn * 32 + nt * 8 + c2;
                int h = n >> 6, e = n & 63;
                float maskv = 1.0f + __ldg(am + (h & 1) * SEQ + sidx) * 1e-4f;
                int mbi = b_ * 16 + h;
                float2 v;
                v.x = (acc[mt][nt][half*2+0] + __ldg(bias + n))     * maskv;
                v.y = (acc[mt][nt][half*2+1] + __ldg(bias + n + 1)) * maskv;
                *(float2*)(out + ((size_t)mbi * SEQ + sidx) * DH + e) = v;
            }
        }
    }
    #undef LOAD_CHUNK
}

// ---------------- K2: block means + token counts ----------------
__global__ void k_stats(const float* __restrict__ am) {
    int mb = blockIdx.y, i = blockIdx.x, e = threadIdx.x; // 64 threads
    float tc = 0.0f;
    int amb = (mb & 1) * SEQ + i * BS;
    for (int t = 0; t < BS; t++) tc += 1.0f + am[amb + t] / 10000.0f;
    float den = tc + 1e-6f;
    const float* Qp = g_Q + ((size_t)mb * SEQ + i * BS) * DH + e;
    const float* Kp = g_K + ((size_t)mb * SEQ + i * BS) * DH + e;
    const float* Vp = g_V + ((size_t)mb * SEQ + i * BS) * DH + e;
    float sq = 0, sk = 0, sv = 0;
    for (int t = 0; t < BS; t++) { sq += Qp[t*DH]; sk += Kp[t*DH]; sv += Vp[t*DH]; }
    int o = (mb * NB + i) * DH + e;
    g_Qh[o] = sq / den; g_Kh[o] = sk / den; g_Vh[o] = sv / den;
    if (e == 0) g_tc[mb * NB + i] = tc;
}

// ---------------- K3: low-res logits, row max, lrn (band added) ----------------
__global__ __launch_bounds__(128) void k_lowlogit() {
    int mb = blockIdx.x, i = threadIdx.x;
    __shared__ float sK[NB * DH];   // 32KB
    __shared__ float sTc[NB];
    for (int t = i; t < NB * DH; t += 128) sK[t] = g_Kh[mb * NB * DH + t];
    if (i < NB) sTc[i] = g_tc[mb * NB + i];
    __syncthreads();

    float qr[DH];
    #pragma unroll
    for (int k = 0; k < DH; k++) qr[k] = g_Qh[(mb * NB + i) * DH + k];

    float row[NB];
    float rmax = -INFINITY;
    for (int j = 0; j < NB; j++) {
        float d = 0.0f;
        #pragma unroll
        for (int k = 0; k < DH; k++) d += qr[k] * sK[j * DH + k];
        d *= 0.125f;
        row[j] = d;
        rmax = fmaxf(rmax, d);       // max BEFORE mask subtraction (matches reference)
    }
    g_rowmax[mb * NB + i] = rmax;
    float tci = sTc[i];
    for (int j = 0; j < NB; j++) {
        float ll = row[j];
        if (tci * sTc[j] < 0.5f) ll -= 10000.0f;
        float lr = ll - rmax;
        int dd = i - j; if (dd < 0) dd = -dd;
        if (dd <= 1) lr += 5000.0f;  // DIAG_N=3 band
        g_ll [(mb * NB + i) * NB + j] = ll;
        g_lrn[(mb * NB + i) * NB + j] = lr;
    }
}

// ---------------- K4: top-512 threshold + per-qb kb lists ----------------
__global__ __launch_bounds__(256) void k_topk() {
    extern __shared__ unsigned skey[];   // 16384 keys = 64KB
    int mb = blockIdx.x, tid = threadIdx.x;
    const float* base = g_lrn + mb * NB * NB;
    __shared__ unsigned sred[256];
    for (int idx = tid; idx < NB * NB; idx += 256) skey[idx] = fkey(base[idx]);
    __syncthreads();
    unsigned lo = 0, hi = 0xFFFFFFFFu;
    while (lo < hi) {
        unsigned mid = (unsigned)(((unsigned long long)lo + (unsigned long long)hi + 1ull) >> 1);
        unsigned c = 0;
        for (int idx = tid; idx < NB * NB; idx += 256) c += (skey[idx] >= mid) ? 1u : 0u;
        sred[tid] = c; __syncthreads();
        for (int off = 128; off; off >>= 1) { if (tid < off) sred[tid] += sred[tid + off]; __syncthreads(); }
        unsigned cnt = sred[0]; __syncthreads();
        if (cnt >= NSEL) lo = mid; else hi = mid - 1;
    }
    if (tid == 0) g_thrkey[mb] = lo;
    for (int idx = tid; idx < NB * NB; idx += 256) {
        if (skey[idx] >= lo) {
            int qb = idx >> 7, kb = idx & 127;
            int p = atomicAdd(&g_qcnt[mb * NB + qb], 1);
            g_qlist[(mb * NB + qb) * NB + p] = kb;
        }
    }
}

// ---------------- K5: fused hi-branch, online softmax per (mb, qb) ----------------
__global__ __launch_bounds__(256) void k_hi(const float* __restrict__ am) {
    int mb = blockIdx.y, qb = blockIdx.x, tid = threadIdx.x;
    int cnt = g_qcnt[mb * NB + qb];
    int q = tid >> 3, g = tid & 7, e0 = g * 8;
    __shared__ float sQ[BS * 68], sK[BS * 68], sV[BS * 68], sL[BS * 33], sMk[BS];
    __shared__ int sList[NB];
    const float* Qg = g_Q + ((size_t)mb * SEQ + qb * BS) * DH;
    for (int t = tid; t < BS * DH; t += 256) sQ[(t >> 6) * 68 + (t & 63)] = Qg[t];
    for (int t = tid; t < cnt; t += 256) sList[t] = g_qlist[(mb * NB + qb) * NB + t];
    __syncthreads();

    float m = -1e8f, nsum = 0.0f;
    float acc[8] = {0,0,0,0,0,0,0,0};
    for (int p = 0; p < cnt; p++) {
        int kb = sList[p];
        const float* Kg = g_K + ((size_t)mb * SEQ + kb * BS) * DH;
        const float* Vg = g_V + ((size_t)mb * SEQ + kb * BS) * DH;
        __syncthreads();
        for (int t = tid; t < BS * DH; t += 256) {
            int r = t >> 6, cc = t & 63;
            sK[r * 68 + cc] = Kg[t];
            sV[r * 68 + cc] = Vg[t];
        }
        if (tid < BS) sMk[tid] = 1.0f + __ldg(am + (mb & 1) * SEQ + kb * BS + tid) * 1e-4f;
        __syncthreads();
        // logits: each thread computes 4 (k) entries for its q
        #pragma unroll
        for (int kk = 0; kk < 4; kk++) {
            int k = g * 4 + kk;
            float d = 0.0f;
            #pragma unroll
            for (int e = 0; e < DH; e++) d += sK[k * 68 + e] * sQ[q * 68 + e];
            sL[k * 33 + q] = d * 0.125f;
        }
        __syncthreads();
        float bm = -1e8f;
        #pragma unroll
        for (int k = 0; k < BS; k++) bm = fmaxf(bm, sL[k * 33 + q]);  // unmasked max (matches ref)
        float newm = fmaxf(m, bm);
        float scale = __expf(m - newm);
        m = newm;
        nsum *= scale;
        #pragma unroll
        for (int j = 0; j < 8; j++) acc[j] *= scale;
        #pragma unroll
        for (int k = 0; k < BS; k++) {
            float a = __expf(sL[k * 33 + q] - m - 10000.0f * (1.0f - sMk[k]));
            nsum += a;
            #pragma unroll
            for (int j = 0; j < 8; j++) acc[j] += a * sV[k * 68 + e0 + j];
        }
    }
    float* dst = g_hiout + ((size_t)mb * SEQ + qb * BS + q) * DH + e0;
    #pragma unroll
    for (int j = 0; j < 8; j++) dst[j] = acc[j];
    if (g == 0) {
        g_hinorm[mb * SEQ + qb * BS + q] = nsum;
        g_maxblkf[(mb * NB + qb) * BS + q] = m;
    }
}

// ---------------- K7: low-res branch (selected blocks suppressed) ----------------
__global__ __launch_bounds__(128) void k_low() {
    int mb = blockIdx.y, i = blockIdx.x, j = threadIdx.x;
    __shared__ float sA[NB];
    __shared__ float sred[NB];
    float thr  = fdecode(g_thrkey[mb]);
    float rmax = g_rowmax[mb * NB + i];
    float ll = g_ll [(mb * NB + i) * NB + j];
    float lr = g_lrn[(mb * NB + i) * NB + j];
    float a = __expf(ll - rmax - ((lr >= thr) ? 10000.0f : 0.0f)) * g_tc[mb * NB + j];
    sA[j] = a; sred[j] = a;
    __syncthreads();
    for (int off = 64; off; off >>= 1) { if (j < off) sred[j] += sred[j + off]; __syncthreads(); }
    if (j == 0) g_lownorm[mb * NB + i] = sred[0];
    if (j < DH) {
        float acc = 0.0f;
        for (int t = 0; t < NB; t++) acc += sA[t] * g_Vh[(mb * NB + t) * DH + j];
        g_lowout[(mb * NB + i) * DH + j] = acc;
    }
}

// ---------------- K8: final combine + head merge ----------------
__global__ void k_combine(const float* __restrict__ am, float* __restrict__ out) {
    int mb = blockIdx.y;
    int s  = blockIdx.x * 4 + (threadIdx.x >> 6);
    int e  = threadIdx.x & 63;
    int i = s >> 5, t = s & 31;
    float maskv = 1.0f + am[(mb & 1) * SEQ + s] / 10000.0f;
    float rm = g_rowmax[mb * NB + i];
    float mv = g_maxblkf[(mb * NB + i) * BS + t];
    float lc = (rm - mv) * maskv;
    float locorr = __expf(fminf(lc, 0.0f));
    float hicorr = __expf(-fmaxf(lc, 0.0f));
    float hn = g_hinorm[mb * SEQ + s] * hicorr;
    float ln = g_lownorm[mb * NB + i] * locorr;
    float den = hn + ln + 1e-6f;
    float v = (g_hiout[((size_t)mb * SEQ + s) * DH + e] * hicorr
             + g_lowout[(mb * NB + i) * DH + e] * locorr) / den * maskv;
    int b = mb >> 4, h = mb & 15;
    out[((size_t)b * SEQ + s) * HDIM + h * DH + e] = v;
}

// ---------------- launch ----------------
extern "C" void kernel_launch(void* const* d_in, const int* in_sizes, int n_in,
                              void* d_out, int out_size) {
    const float* X  = (const float*)d_in[0];
    const float* am = (const float*)d_in[1];
    const float* wq = (const float*)d_in[2];
    const float* bq = (const float*)d_in[3];
    const float* wk = (const float*)d_in[4];
    const float* bk = (const float*)d_in[5];
    const float* wv = (const float*)d_in[6];
    const float* bv = (const float*)d_in[7];
    float* out = (float*)d_out;

    void *pXhi, *pXlo, *pWhi, *pWlo;
    cudaGetSymbolAddress(&pXhi, g_Xhi);
    cudaGetSymbolAddress(&pXlo, g_Xlo);
    cudaGetSymbolAddress(&pWhi, g_Whi);
    cudaGetSymbolAddress(&pWlo, g_Wlo);

    cudaFuncSetAttribute(k_gemm_mma, cudaFuncAttributeMaxDynamicSharedMemorySize, GEMM_SMEM);
    cudaFuncSetAttribute(k_topk, cudaFuncAttributeMaxDynamicSharedMemorySize, 65536);

    // launches 1-5 (so launch 6, profiled by ncu -s 5, is the GEMM)
    int nx4 = MROWS * HDIM / 4;
    int nw4 = HDIM * HDIM / 4;
    k_split<<<(nx4 + 255) / 256, 256>>>((const float4*)X,  (__nv_bfloat162*)pXhi, (__nv_bfloat162*)pXlo, nx4);
    k_split<<<(nw4 + 255) / 256, 256>>>((const float4*)wq, (__nv_bfloat162*)pWhi, (__nv_bfloat162*)pWlo, nw4);
    k_split<<<(nw4 + 255) / 256, 256>>>((const float4*)wk,
        (__nv_bfloat162*)((char*)pWhi + (size_t)HDIM*HDIM*2), (__nv_bfloat162*)((char*)pWlo + (size_t)HDIM*HDIM*2), nw4);
    k_split<<<(nw4 + 255) / 256, 256>>>((const float4*)wv,
        (__nv_bfloat162*)((char*)pWhi + (size_t)2*HDIM*HDIM*2), (__nv_bfloat162*)((char*)pWlo + (size_t)2*HDIM*HDIM*2), nw4);
    k_zero<<<(MB * NB + 255) / 256, 256>>>();

    k_gemm_mma<<<dim3(HDIM / 128, MROWS / 128, 3), 256, GEMM_SMEM>>>(am, bq, bk, bv);

    k_stats<<<dim3(NB, MB), 64>>>(am);
    k_lowlogit<<<MB, 128>>>();
    k_topk<<<MB, 256, 65536>>>();
    k_hi<<<dim3(NB, MB), 256>>>(am);
    k_low<<<dim3(NB, MB), 128>>>();
    k_combine<<<dim3(SEQ / 4, MB), 256>>>(am, out);
}

// round 5
// speedup vs baseline: 1.7117x; 1.0154x over previous
#include <cuda_runtime.h>
#include <cuda_bf16.h>
#include <math.h>
#include <stdint.h>

// ---------------- problem constants ----------------
#define MB    32      // meta-batch = batch(2) * heads(16)
#define SEQ   4096
#define DH    64      // head dim
#define NB    128     // seq / 32 blocks
#define BS    32      // block size
#define NSEL  512     // NUM_BLOCKS
#define HDIM  1024
#define MROWS 8192    // batch * seq

// ---------------- scratch (device globals; no allocation allowed) ----------------
__device__ float    g_Q[(size_t)MB*SEQ*DH];
__device__ float    g_K[(size_t)MB*SEQ*DH];
__device__ float    g_V[(size_t)MB*SEQ*DH];
__device__ __nv_bfloat16 g_Xhi[(size_t)MROWS*HDIM];
__device__ __nv_bfloat16 g_Xlo[(size_t)MROWS*HDIM];
__device__ __nv_bfloat16 g_Whi[(size_t)3*HDIM*HDIM];
__device__ __nv_bfloat16 g_Wlo[(size_t)3*HDIM*HDIM];
__device__ float    g_Qh[MB*NB*DH];
__device__ float    g_Kh[MB*NB*DH];
__device__ float    g_Vh[MB*NB*DH];
__device__ float    g_tc[MB*NB];
__device__ float    g_ll[MB*NB*NB];      // masked low-res logits
__device__ float    g_lrn[MB*NB*NB];     // lrn (logit - rowmax + band)
__device__ float    g_rowmax[MB*NB];
__device__ unsigned g_thrkey[MB];
__device__ int      g_qcnt[MB*NB];       // selected kb count per (mb, qb)
__device__ int      g_qlist[MB*NB*NB];   // kb list per (mb, qb)
__device__ float    g_maxblkf[MB*NB*BS]; // per-query-row max over selected blocks
__device__ float    g_hiout[(size_t)MB*SEQ*DH];
__device__ float    g_hinorm[MB*SEQ];
__device__ float    g_lowout[MB*NB*DH];
__device__ float    g_lownorm[MB*NB];

// order-preserving float <-> uint mapping
__device__ __forceinline__ unsigned fkey(float f) {
    unsigned u = __float_as_uint(f);
    return (u & 0x80000000u) ? ~u : (u | 0x80000000u);
}
__device__ __forceinline__ float fdecode(unsigned k) {
    unsigned u = (k & 0x80000000u) ? (k & 0x7FFFFFFFu) : ~k;
    return __uint_as_float(u);
}

__device__ __forceinline__ uint32_t smem_u32(const void* p) {
    uint32_t a;
    asm("{ .reg .u64 t; cvta.to.shared.u64 t, %1; cvt.u32.u64 %0, t; }" : "=r"(a) : "l"(p));
    return a;
}

#define LDSM4(r, a) \
    asm volatile("ldmatrix.sync.aligned.m8n8.x4.shared.b16 {%0,%1,%2,%3}, [%4];" \
        : "=r"((r)[0]), "=r"((r)[1]), "=r"((r)[2]), "=r"((r)[3]) : "r"(a))

#define MMA16816(d, a, b0, b1) \
    asm volatile("mma.sync.aligned.m16n8k16.row.col.f32.bf16.bf16.f32 " \
        "{%0,%1,%2,%3}, {%4,%5,%6,%7}, {%8,%9}, {%0,%1,%2,%3};" \
        : "+f"((d)[0]), "+f"((d)[1]), "+f"((d)[2]), "+f"((d)[3]) \
        : "r"((a)[0]), "r"((a)[1]), "r"((a)[2]), "r"((a)[3]), "r"(b0), "r"(b1))

#define CP16(saddr, gptr) \
    asm volatile("cp.async.cg.shared.global [%0], [%1], 16;" :: "r"(saddr), "l"(gptr) : "memory")
#define CP_COMMIT() asm volatile("cp.async.commit_group;" ::: "memory")
#define CP_WAIT1()  asm volatile("cp.async.wait_group 1;" ::: "memory")
#define CP_WAIT0()  asm volatile("cp.async.wait_group 0;" ::: "memory")

// ---------------- K0: fp32 -> bf16 hi/lo split ----------------
__global__ void k_split(const float4* __restrict__ src, __nv_bfloat162* __restrict__ hi,
                        __nv_bfloat162* __restrict__ lo, int n4) {
    int i = blockIdx.x * blockDim.x + threadIdx.x;
    if (i >= n4) return;
    float4 v = src[i];
    __nv_bfloat16 h0 = __float2bfloat16(v.x), h1 = __float2bfloat16(v.y);
    __nv_bfloat16 h2 = __float2bfloat16(v.z), h3 = __float2bfloat16(v.w);
    __nv_bfloat16 l0 = __float2bfloat16(v.x - __bfloat162float(h0));
    __nv_bfloat16 l1 = __float2bfloat16(v.y - __bfloat162float(h1));
    __nv_bfloat16 l2 = __float2bfloat16(v.z - __bfloat162float(h2));
    __nv_bfloat16 l3 = __float2bfloat16(v.w - __bfloat162float(h3));
    hi[2*i]   = __halves2bfloat162(h0, h1);
    hi[2*i+1] = __halves2bfloat162(h2, h3);
    lo[2*i]   = __halves2bfloat162(l0, l1);
    lo[2*i+1] = __halves2bfloat162(l2, l3);
}

// ---------------- K0b: zero small counters ----------------
__global__ void k_zero() {
    int i = blockIdx.x * blockDim.x + threadIdx.x;
    if (i < MB * NB) g_qcnt[i] = 0;
}

// ---------------- K1: bf16 mma.sync QKV projection GEMM ----------------
// CTA 128x256, 8 warps (2m x 4n), warp tile 64x64. K-chunk 32, 2-stage cp.async.
// 2-term split: acc = Ah*Bh + Al*Bh + Ah*Bl (frag-register reuse).
#define KCH      32
#define RSTRIDE  80                 // bytes per smem row (64B data + 16 pad)
#define A_T      10240              // 128 rows * 80
#define B_T      20480              // 256 rows * 80
#define STAGE_B  (2*A_T + 2*B_T)    // 61440: Ah, Al, Bh, Bl
#define NCHUNK   (HDIM / KCH)       // 32
#define GEMM_SMEM (2 * STAGE_B)     // 122880
#define OFF_AH   0
#define OFF_AL   A_T
#define OFF_BH   (2*A_T)
#define OFF_BL   (2*A_T + B_T)

__global__ __launch_bounds__(256, 1) void k_gemm_mma(
    const float* __restrict__ am, const float* __restrict__ bq,
    const float* __restrict__ bk, const float* __restrict__ bv)
{
    extern __shared__ char sm_[];
    uint32_t sb = smem_u32(sm_);
    int tid = threadIdx.x, lid = tid & 31, wid = tid >> 5;
    int wm = wid >> 2, wn = wid & 3;
    int proj = blockIdx.z;
    int n0 = blockIdx.x * 256, m0 = blockIdx.y * 128;

    const __nv_bfloat16* Ahp = g_Xhi;
    const __nv_bfloat16* Alp = g_Xlo;
    const __nv_bfloat16* Bhp = g_Whi + (size_t)proj * HDIM * HDIM;
    const __nv_bfloat16* Blp = g_Wlo + (size_t)proj * HDIM * HDIM;
    const float* bias = (proj == 0) ? bq : ((proj == 1) ? bk : bv);
    float* out = (proj == 0) ? g_Q : ((proj == 1) ? g_K : g_V);

    float acc[4][8][4];
    #pragma unroll
    for (int mt = 0; mt < 4; mt++)
        #pragma unroll
        for (int nt = 0; nt < 8; nt++)
            #pragma unroll
            for (int r = 0; r < 4; r++) acc[mt][nt][r] = 0.0f;

    #define LOAD_CHUNK(ch, s) do {                                              \
        uint32_t st_ = sb + (s) * STAGE_B;                                      \
        int gk_ = (ch) * KCH;                                                   \
        _Pragma("unroll")                                                       \
        for (int j = 0; j < 2; j++) {                                           \
            int u = tid + j * 256;                                              \
            int row = u >> 2, kc = u & 3;                                       \
            uint32_t so = row * RSTRIDE + kc * 16;                              \
            size_t ga = (size_t)(m0 + row) * HDIM + gk_ + kc * 8;               \
            CP16(st_ + OFF_AH + so, Ahp + ga);                                  \
            CP16(st_ + OFF_AL + so, Alp + ga);                                  \
        }                                                                       \
        _Pragma("unroll")                                                       \
        for (int j = 0; j < 4; j++) {                                           \
            int u = tid + j * 256;                                              \
            int row = u >> 2, kc = u & 3;                                       \
            uint32_t so = row * RSTRIDE + kc * 16;                              \
            size_t gb = (size_t)(n0 + row) * HDIM + gk_ + kc * 8;               \
            CP16(st_ + OFF_BH + so, Bhp + gb);                                  \
            CP16(st_ + OFF_BL + so, Blp + gb);                                  \
        }                                                                       \
        CP_COMMIT();                                                            \
    } while (0)

    LOAD_CHUNK(0, 0);
    LOAD_CHUNK(1, 1);

    int g = lid >> 3, lr = lid & 7;
    int a_roff = lr + (g & 1) * 8;
    int a_koff = (g >> 1) * 16;
    int b_roff = lr + (g >> 1) * 8;
    int b_koff = (g & 1) * 16;

    for (int ch = 0; ch < NCHUNK; ch++) {
        int s = ch & 1;
        if (ch < NCHUNK - 1) { CP_WAIT1(); } else { CP_WAIT0(); }
        __syncthreads();
        uint32_t st = sb + s * STAGE_B;
        #pragma unroll
        for (int ks = 0; ks < 2; ks++) {
            uint32_t koff = ks * 32;
            uint32_t aa[4][4], bb[4][4];
            uint32_t a_base = st + (wm * 64 + a_roff) * RSTRIDE + koff + a_koff;
            uint32_t b_base = st + (wn * 64 + b_roff) * RSTRIDE + koff + b_koff;
            // ---- pass 1: Ah x Bh ----
            #pragma unroll
            for (int mt = 0; mt < 4; mt++) LDSM4(aa[mt], a_base + OFF_AH + mt * 16 * RSTRIDE);
            #pragma unroll
            for (int np = 0; np < 4; np++) LDSM4(bb[np], b_base + OFF_BH + np * 16 * RSTRIDE);
            #pragma unroll
            for (int mt = 0; mt < 4; mt++)
                #pragma unroll
                for (int np = 0; np < 4; np++) {
                    MMA16816(acc[mt][2*np+0], aa[mt], bb[np][0], bb[np][1]);
                    MMA16816(acc[mt][2*np+1], aa[mt], bb[np][2], bb[np][3]);
                }
            // ---- pass 2: Al x Bh (reuse aa) ----
            #pragma unroll
            for (int mt = 0; mt < 4; mt++) LDSM4(aa[mt], a_base + OFF_AL + mt * 16 * RSTRIDE);
            #pragma unroll
            for (int mt = 0; mt < 4; mt++)
                #pragma unroll
                for (int np = 0; np < 4; np++) {
                    MMA16816(acc[mt][2*np+0], aa[mt], bb[np][0], bb[np][1]);
                    MMA16816(acc[mt][2*np+1], aa[mt], bb[np][2], bb[np][3]);
                }
            // ---- pass 3: Ah x Bl (reuse bb, reload Ah) ----
            #pragma unroll
            for (int np = 0; np < 4; np++) LDSM4(bb[np], b_base + OFF_BL + np * 16 * RSTRIDE);
            #pragma unroll
            for (int mt = 0; mt < 4; mt++) LDSM4(aa[mt], a_base + OFF_AH + mt * 16 * RSTRIDE);
            #pragma unroll
            for (int mt = 0; mt < 4; mt++)
                #pragma unroll
                for (int np = 0; np < 4; np++) {
                    MMA16816(acc[mt][2*np+0], aa[mt], bb[np][0], bb[np][1]);
                    MMA16816(acc[mt][2*np+1], aa[mt], bb[np][2], bb[np][3]);
                }
        }
        __syncthreads();
        if (ch + 2 < NCHUNK) LOAD_CHUNK(ch + 2, s);
    }

    // ---- epilogue: +bias, *mask, head-split scatter. h constant per warp ----
    int h = blockIdx.x * 4 + wn;
    int r4 = lid >> 2, c2 = (lid & 3) * 2;
    const float* amrow = am + (h & 1) * SEQ;
    #pragma unroll
    for (int mt = 0; mt < 4; mt++) {
        #pragma unroll
        for (int half = 0; half < 2; half++) {
            int m = m0 + wm * 64 + mt * 16 + r4 + half * 8;
            int b_ = m >> 12, sidx = m & 4095;
            float maskv = 1.0f + __ldg(amrow + sidx) * 1e-4f;
            int mbi = b_ * 16 + h;
            float* op = out + ((size_t)mbi * SEQ + sidx) * DH;
            #pragma unroll
            for (int nt = 0; nt < 8; nt++) {
                int e = nt * 8 + c2;
                float2 v;
                v.x = (acc[mt][nt][half*2+0] + __ldg(bias + h * 64 + e))     * maskv;
                v.y = (acc[mt][nt][half*2+1] + __ldg(bias + h * 64 + e + 1)) * maskv;
                *(float2*)(op + e) = v;
            }
        }
    }
    #undef LOAD_CHUNK
}

// ---------------- K2: block means + token counts ----------------
__global__ void k_stats(const float* __restrict__ am) {
    int mb = blockIdx.y, i = blockIdx.x, e = threadIdx.x; // 64 threads
    float tc = 0.0f;
    int amb = (mb & 1) * SEQ + i * BS;
    for (int t = 0; t < BS; t++) tc += 1.0f + am[amb + t] / 10000.0f;
    float den = tc + 1e-6f;
    const float* Qp = g_Q + ((size_t)mb * SEQ + i * BS) * DH + e;
    const float* Kp = g_K + ((size_t)mb * SEQ + i * BS) * DH + e;
    const float* Vp = g_V + ((size_t)mb * SEQ + i * BS) * DH + e;
    float sq = 0, sk = 0, sv = 0;
    for (int t = 0; t < BS; t++) { sq += Qp[t*DH]; sk += Kp[t*DH]; sv += Vp[t*DH]; }
    int o = (mb * NB + i) * DH + e;
    g_Qh[o] = sq / den; g_Kh[o] = sk / den; g_Vh[o] = sv / den;
    if (e == 0) g_tc[mb * NB + i] = tc;
}

// ---------------- K3: low-res logits, row max, lrn (no per-thread array) ----------------
__global__ __launch_bounds__(128) void k_lowlogit() {
    int mb = blockIdx.x, i = threadIdx.x;
    __shared__ float sK[NB * DH];   // 32KB
    __shared__ float sTc[NB];
    for (int t = i; t < NB * DH; t += 128) sK[t] = g_Kh[mb * NB * DH + t];
    if (i < NB) sTc[i] = g_tc[mb * NB + i];
    __syncthreads();

    float qr[DH];
    #pragma unroll
    for (int k = 0; k < DH; k++) qr[k] = g_Qh[(mb * NB + i) * DH + k];

    float* llrow = g_ll + (mb * NB + i) * NB;
    float rmax = -INFINITY;
    for (int j = 0; j < NB; j++) {
        float d = 0.0f;
        #pragma unroll
        for (int k = 0; k < DH; k++) d += qr[k] * sK[j * DH + k];
        d *= 0.125f;
        llrow[j] = d;                // raw logit (pre-mask); same thread re-reads below
        rmax = fmaxf(rmax, d);       // max BEFORE mask subtraction (matches reference)
    }
    g_rowmax[mb * NB + i] = rmax;
    float tci = sTc[i];
    float* lrow = g_lrn + (mb * NB + i) * NB;
    for (int j = 0; j < NB; j++) {
        float ll = llrow[j];
        if (tci * sTc[j] < 0.5f) ll -= 10000.0f;
        float lr = ll - rmax;
        int dd = i - j; if (dd < 0) dd = -dd;
        if (dd <= 1) lr += 5000.0f;  // DIAG_N=3 band
        llrow[j] = ll;
        lrow[j] = lr;
    }
}

// ---------------- K4: top-512 threshold + per-qb kb lists ----------------
__global__ __launch_bounds__(256) void k_topk() {
    extern __shared__ unsigned skey[];   // 16384 keys = 64KB
    int mb = blockIdx.x, tid = threadIdx.x;
    const float* base = g_lrn + mb * NB * NB;
    __shared__ unsigned sred[256];
    for (int idx = tid; idx < NB * NB; idx += 256) skey[idx] = fkey(base[idx]);
    __syncthreads();
    unsigned lo = 0, hi = 0xFFFFFFFFu;
    while (lo < hi) {
        unsigned mid = (unsigned)(((unsigned long long)lo + (unsigned long long)hi + 1ull) >> 1);
        unsigned c = 0;
        for (int idx = tid; idx < NB * NB; idx += 256) c += (skey[idx] >= mid) ? 1u : 0u;
        sred[tid] = c; __syncthreads();
        for (int off = 128; off; off >>= 1) { if (tid < off) sred[tid] += sred[tid + off]; __syncthreads(); }
        unsigned cnt = sred[0]; __syncthreads();
        if (cnt >= NSEL) lo = mid; else hi = mid - 1;
    }
    if (tid == 0) g_thrkey[mb] = lo;
    for (int idx = tid; idx < NB * NB; idx += 256) {
        if (skey[idx] >= lo) {
            int qb = idx >> 7, kb = idx & 127;
            int p = atomicAdd(&g_qcnt[mb * NB + qb], 1);
            g_qlist[(mb * NB + qb) * NB + p] = kb;
        }
    }
}

// ---------------- K5: fused hi-branch, online softmax per (mb, qb) ----------------
__global__ __launch_bounds__(256) void k_hi(const float* __restrict__ am) {
    int mb = blockIdx.y, qb = blockIdx.x, tid = threadIdx.x;
    int cnt = g_qcnt[mb * NB + qb];
    int q = tid >> 3, g = tid & 3 | ((tid & 7) & 7); g = tid & 7;
    int e0 = g * 8;
    __shared__ float sQ[BS * 68], sK[BS * 68], sV[BS * 68], sL[BS * 33], sMk[BS];
    __shared__ int sList[NB];
    const float* Qg = g_Q + ((size_t)mb * SEQ + qb * BS) * DH;
    for (int t = tid; t < BS * DH / 4; t += 256) {
        int r = t >> 4, cc = (t & 15) * 4;
        *(float4*)&sQ[r * 68 + cc] = ((const float4*)Qg)[t];
    }
    for (int t = tid; t < cnt; t += 256) sList[t] = g_qlist[(mb * NB + qb) * NB + t];
    __syncthreads();

    float m = -1e8f, nsum = 0.0f;
    float acc[8] = {0,0,0,0,0,0,0,0};
    for (int p = 0; p < cnt; p++) {
        int kb = sList[p];
        const float* Kg = g_K + ((size_t)mb * SEQ + kb * BS) * DH;
        const float* Vg = g_V + ((size_t)mb * SEQ + kb * BS) * DH;
        __syncthreads();
        for (int t = tid; t < BS * DH / 4; t += 256) {
            int r = t >> 4, cc = (t & 15) * 4;
            *(float4*)&sK[r * 68 + cc] = ((const float4*)Kg)[t];
            *(float4*)&sV[r * 68 + cc] = ((const float4*)Vg)[t];
        }
        if (tid < BS) sMk[tid] = 1.0f + __ldg(am + (mb & 1) * SEQ + kb * BS + tid) * 1e-4f;
        __syncthreads();
        #pragma unroll
        for (int kk = 0; kk < 4; kk++) {
            int k = g * 4 + kk;
            float d = 0.0f;
            #pragma unroll
            for (int e = 0; e < DH; e++) d += sK[k * 68 + e] * sQ[q * 68 + e];
            sL[k * 33 + q] = d * 0.125f;
        }
        __syncthreads();
        float bm = -1e8f;
        #pragma unroll
        for (int k = 0; k < BS; k++) bm = fmaxf(bm, sL[k * 33 + q]);  // unmasked max (matches ref)
        float newm = fmaxf(m, bm);
        float scale = __expf(m - newm);
        m = newm;
        nsum *= scale;
        #pragma unroll
        for (int j = 0; j < 8; j++) acc[j] *= scale;
        #pragma unroll
        for (int k = 0; k < BS; k++) {
            float a = __expf(sL[k * 33 + q] - m - 10000.0f * (1.0f - sMk[k]));
            nsum += a;
            #pragma unroll
            for (int j = 0; j < 8; j++) acc[j] += a * sV[k * 68 + e0 + j];
        }
    }
    float* dst = g_hiout + ((size_t)mb * SEQ + qb * BS + q) * DH + e0;
    #pragma unroll
    for (int j = 0; j < 8; j++) dst[j] = acc[j];
    if (g == 0) {
        g_hinorm[mb * SEQ + qb * BS + q] = nsum;
        g_maxblkf[(mb * NB + qb) * BS + q] = m;
    }
}

// ---------------- K7: low-res branch (selected blocks suppressed) ----------------
__global__ __launch_bounds__(128) void k_low() {
    int mb = blockIdx.y, i = blockIdx.x, j = threadIdx.x;
    __shared__ float sA[NB];
    __shared__ float sred[NB];
    float thr  = fdecode(g_thrkey[mb]);
    float rmax = g_rowmax[mb * NB + i];
    float ll = g_ll [(mb * NB + i) * NB + j];
    float lr = g_lrn[(mb * NB + i) * NB + j];
    float a = __expf(ll - rmax - ((lr >= thr) ? 10000.0f : 0.0f)) * g_tc[mb * NB + j];
    sA[j] = a; sred[j] = a;
    __syncthreads();
    for (int off = 64; off; off >>= 1) { if (j < off) sred[j] += sred[j + off]; __syncthreads(); }
    if (j == 0) g_lownorm[mb * NB + i] = sred[0];
    if (j < DH) {
        float acc = 0.0f;
        for (int t = 0; t < NB; t++) acc += sA[t] * g_Vh[(mb * NB + t) * DH + j];
        g_lowout[(mb * NB + i) * DH + j] = acc;
    }
}

// ---------------- K8: final combine + head merge ----------------
__global__ void k_combine(const float* __restrict__ am, float* __restrict__ out) {
    int mb = blockIdx.y;
    int s  = blockIdx.x * 4 + (threadIdx.x >> 6);
    int e  = threadIdx.x & 63;
    int i = s >> 5, t = s & 31;
    float maskv = 1.0f + am[(mb & 1) * SEQ + s] / 10000.0f;
    float rm = g_rowmax[mb * NB + i];
    float mv = g_maxblkf[(mb * NB + i) * BS + t];
    float lc = (rm - mv) * maskv;
    float locorr = __expf(fminf(lc, 0.0f));
    float hicorr = __expf(-fmaxf(lc, 0.0f));
    float hn = g_hinorm[mb * SEQ + s] * hicorr;
    float ln = g_lownorm[mb * NB + i] * locorr;
    float den = hn + ln + 1e-6f;
    float v = (g_hiout[((size_t)mb * SEQ + s) * DH + e] * hicorr
             + g_lowout[(mb * NB + i) * DH + e] * locorr) / den * maskv;
    int b = mb >> 4, h = mb & 15;
    out[((size_t)b * SEQ + s) * HDIM + h * DH + e] = v;
}

// ---------------- launch ----------------
extern "C" void kernel_launch(void* const* d_in, const int* in_sizes, int n_in,
                              void* d_out, int out_size) {
    const float* X  = (const float*)d_in[0];
    const float* am = (const float*)d_in[1];
    const float* wq = (const float*)d_in[2];
    const float* bq = (const float*)d_in[3];
    const float* wk = (const float*)d_in[4];
    const float* bk = (const float*)d_in[5];
    const float* wv = (const float*)d_in[6];
    const float* bv = (const float*)d_in[7];
    float* out = (float*)d_out;

    void *pXhi, *pXlo, *pWhi, *pWlo;
    cudaGetSymbolAddress(&pXhi, g_Xhi);
    cudaGetSymbolAddress(&pXlo, g_Xlo);
    cudaGetSymbolAddress(&pWhi, g_Whi);
    cudaGetSymbolAddress(&pWlo, g_Wlo);

    cudaFuncSetAttribute(k_gemm_mma, cudaFuncAttributeMaxDynamicSharedMemorySize, GEMM_SMEM);
    cudaFuncSetAttribute(k_topk, cudaFuncAttributeMaxDynamicSharedMemorySize, 65536);

    int nx4 = MROWS * HDIM / 4;
    int nw4 = HDIM * HDIM / 4;
    k_split<<<(nx4 + 255) / 256, 256>>>((const float4*)X,  (__nv_bfloat162*)pXhi, (__nv_bfloat162*)pXlo, nx4);
    k_split<<<(nw4 + 255) / 256, 256>>>((const float4*)wq, (__nv_bfloat162*)pWhi, (__nv_bfloat162*)pWlo, nw4);
    k_split<<<(nw4 + 255) / 256, 256>>>((const float4*)wk,
        (__nv_bfloat162*)((char*)pWhi + (size_t)HDIM*HDIM*2), (__nv_bfloat162*)((char*)pWlo + (size_t)HDIM*HDIM*2), nw4);
    k_split<<<(nw4 + 255) / 256, 256>>>((const float4*)wv,
        (__nv_bfloat162*)((char*)pWhi + (size_t)2*HDIM*HDIM*2), (__nv_bfloat162*)((char*)pWlo + (size_t)2*HDIM*HDIM*2), nw4);
    k_zero<<<(MB * NB + 255) / 256, 256>>>();

    k_gemm_mma<<<dim3(HDIM / 256, MROWS / 128, 3), 256, GEMM_SMEM>>>(am, bq, bk, bv);

    k_stats<<<dim3(NB, MB), 64>>>(am);
    k_lowlogit<<<MB, 128>>>();
    k_topk<<<MB, 256, 65536>>>();
    k_hi<<<dim3(NB, MB), 256>>>(am);
    k_low<<<dim3(NB, MB), 128>>>();
    k_combine<<<dim3(SEQ / 4, MB), 256>>>(am, out);
}

// round 6
// speedup vs baseline: 2.4950x; 1.4576x over previous
#include <cuda_runtime.h>
#include <cuda_fp16.h>
#include <math.h>
#include <stdint.h>

// ---------------- problem constants ----------------
#define MB    32      // meta-batch = batch(2) * heads(16)
#define SEQ   4096
#define DH    64      // head dim
#define NB    128     // seq / 32 blocks
#define BS    32      // block size
#define NSEL  512     // NUM_BLOCKS
#define HDIM  1024
#define MROWS 8192    // batch * seq

// ---------------- scratch (device globals; no allocation allowed) ----------------
__device__ float    g_Q[(size_t)MB*SEQ*DH];
__device__ float    g_K[(size_t)MB*SEQ*DH];
__device__ float    g_V[(size_t)MB*SEQ*DH];
__device__ __half   g_Xhi[(size_t)MROWS*HDIM];
__device__ __half   g_Xlo[(size_t)MROWS*HDIM];
__device__ __half   g_Whi[(size_t)3*HDIM*HDIM];
__device__ __half   g_Wlo[(size_t)3*HDIM*HDIM];   // written by split, unused by GEMM
__device__ float    g_Qh[MB*NB*DH];
__device__ float    g_Kh[MB*NB*DH];
__device__ float    g_Vh[MB*NB*DH];
__device__ float    g_tc[MB*NB];
__device__ float    g_ll[MB*NB*NB];      // masked low-res logits
__device__ float    g_lrn[MB*NB*NB];     // lrn (logit - rowmax + band)
__device__ float    g_rowmax[MB*NB];
__device__ unsigned g_thrkey[MB];
__device__ int      g_qcnt[MB*NB];       // selected kb count per (mb, qb)
__device__ int      g_qlist[MB*NB*NB];   // kb list per (mb, qb)
__device__ float    g_maxblkf[MB*NB*BS]; // per-query-row max over selected blocks
__device__ float    g_hiout[(size_t)MB*SEQ*DH];
__device__ float    g_hinorm[MB*SEQ];
__device__ float    g_lowout[MB*NB*DH];
__device__ float    g_lownorm[MB*NB];

// order-preserving float <-> uint mapping
__device__ __forceinline__ unsigned fkey(float f) {
    unsigned u = __float_as_uint(f);
    return (u & 0x80000000u) ? ~u : (u | 0x80000000u);
}
__device__ __forceinline__ float fdecode(unsigned k) {
    unsigned u = (k & 0x80000000u) ? (k & 0x7FFFFFFFu) : ~k;
    return __uint_as_float(u);
}

__device__ __forceinline__ uint32_t smem_u32(const void* p) {
    uint32_t a;
    asm("{ .reg .u64 t; cvta.to.shared.u64 t, %1; cvt.u32.u64 %0, t; }" : "=r"(a) : "l"(p));
    return a;
}

#define LDSM4(r, a) \
    asm volatile("ldmatrix.sync.aligned.m8n8.x4.shared.b16 {%0,%1,%2,%3}, [%4];" \
        : "=r"((r)[0]), "=r"((r)[1]), "=r"((r)[2]), "=r"((r)[3]) : "r"(a))

#define MMA16816(d, a, b0, b1) \
    asm volatile("mma.sync.aligned.m16n8k16.row.col.f32.f16.f16.f32 " \
        "{%0,%1,%2,%3}, {%4,%5,%6,%7}, {%8,%9}, {%0,%1,%2,%3};" \
        : "+f"((d)[0]), "+f"((d)[1]), "+f"((d)[2]), "+f"((d)[3]) \
        : "r"((a)[0]), "r"((a)[1]), "r"((a)[2]), "r"((a)[3]), "r"(b0), "r"(b1))

#define CP16(saddr, gptr) \
    asm volatile("cp.async.cg.shared.global [%0], [%1], 16;" :: "r"(saddr), "l"(gptr) : "memory")
#define CP_COMMIT() asm volatile("cp.async.commit_group;" ::: "memory")
#define CP_WAIT1()  asm volatile("cp.async.wait_group 1;" ::: "memory")
#define CP_WAIT0()  asm volatile("cp.async.wait_group 0;" ::: "memory")

// ---------------- K0: fp32 -> fp16 hi/lo split ----------------
__global__ void k_split(const float4* __restrict__ src, __half2* __restrict__ hi,
                        __half2* __restrict__ lo, int n4) {
    int i = blockIdx.x * blockDim.x + threadIdx.x;
    if (i >= n4) return;
    float4 v = src[i];
    __half h0 = __float2half(v.x), h1 = __float2half(v.y);
    __half h2 = __float2half(v.z), h3 = __float2half(v.w);
    __half l0 = __float2half(v.x - __half2float(h0));
    __half l1 = __float2half(v.y - __half2float(h1));
    __half l2 = __float2half(v.z - __half2float(h2));
    __half l3 = __float2half(v.w - __half2float(h3));
    hi[2*i]   = __halves2half2(h0, h1);
    hi[2*i+1] = __halves2half2(h2, h3);
    lo[2*i]   = __halves2half2(l0, l1);
    lo[2*i+1] = __halves2half2(l2, l3);
}

// ---------------- K0b: zero small counters ----------------
__global__ void k_zero() {
    int i = blockIdx.x * blockDim.x + threadIdx.x;
    if (i < MB * NB) g_qcnt[i] = 0;
}

// ---------------- K1: fp16 mma.sync QKV projection GEMM ----------------
// CTA 128x256, 8 warps (2m x 4n), warp tile 64x64. K-chunk 32, 2-stage cp.async.
// 2-pass fp16 split: acc = Ah*Bh + Al*Bh (Ah*Bl dropped, ~2^-11 relative).
#define KCH      32
#define RSTRIDE  80                 // bytes per smem row (64B data + 16 pad)
#define A_T      10240              // 128 rows * 80
#define B_T      20480              // 256 rows * 80
#define STAGE_B  (2*A_T + B_T)      // 40960: Ah, Al, Bh
#define NCHUNK   (HDIM / KCH)       // 32
#define GEMM_SMEM (2 * STAGE_B)     // 81920
#define OFF_AH   0
#define OFF_AL   A_T
#define OFF_BH   (2*A_T)

__global__ __launch_bounds__(256, 1) void k_gemm_mma(
    const float* __restrict__ am, const float* __restrict__ bq,
    const float* __restrict__ bk, const float* __restrict__ bv)
{
    extern __shared__ char sm_[];
    uint32_t sb = smem_u32(sm_);
    int tid = threadIdx.x, lid = tid & 31, wid = tid >> 5;
    int wm = wid >> 2, wn = wid & 3;
    int proj = blockIdx.z;
    int n0 = blockIdx.x * 256, m0 = blockIdx.y * 128;

    const __half* Ahp = g_Xhi;
    const __half* Alp = g_Xlo;
    const __half* Bhp = g_Whi + (size_t)proj * HDIM * HDIM;
    const float* bias = (proj == 0) ? bq : ((proj == 1) ? bk : bv);
    float* out = (proj == 0) ? g_Q : ((proj == 1) ? g_K : g_V);

    float acc[4][8][4];
    #pragma unroll
    for (int mt = 0; mt < 4; mt++)
        #pragma unroll
        for (int nt = 0; nt < 8; nt++)
            #pragma unroll
            for (int r = 0; r < 4; r++) acc[mt][nt][r] = 0.0f;

    #define LOAD_CHUNK(ch, s) do {                                              \
        uint32_t st_ = sb + (s) * STAGE_B;                                      \
        int gk_ = (ch) * KCH;                                                   \
        _Pragma("unroll")                                                       \
        for (int j = 0; j < 2; j++) {                                           \
            int u = tid + j * 256;                                              \
            int row = u >> 2, kc = u & 3;                                       \
            uint32_t so = row * RSTRIDE + kc * 16;                              \
            size_t ga = (size_t)(m0 + row) * HDIM + gk_ + kc * 8;               \
            CP16(st_ + OFF_AH + so, Ahp + ga);                                  \
            CP16(st_ + OFF_AL + so, Alp + ga);                                  \
        }                                                                       \
        _Pragma("unroll")                                                       \
        for (int j = 0; j < 4; j++) {                                           \
            int u = tid + j * 256;                                              \
            int row = u >> 2, kc = u & 3;                                       \
            uint32_t so = row * RSTRIDE + kc * 16;                              \
            size_t gb = (size_t)(n0 + row) * HDIM + gk_ + kc * 8;               \
            CP16(st_ + OFF_BH + so, Bhp + gb);                                  \
        }                                                                       \
        CP_COMMIT();                                                            \
    } while (0)

    LOAD_CHUNK(0, 0);
    LOAD_CHUNK(1, 1);

    int g = lid >> 3, lr = lid & 7;
    int a_roff = lr + (g & 1) * 8;
    int a_koff = (g >> 1) * 16;
    int b_roff = lr + (g >> 1) * 8;
    int b_koff = (g & 1) * 16;

    for (int ch = 0; ch < NCHUNK; ch++) {
        int s = ch & 1;
        if (ch < NCHUNK - 1) { CP_WAIT1(); } else { CP_WAIT0(); }
        __syncthreads();
        uint32_t st = sb + s * STAGE_B;
        #pragma unroll
        for (int ks = 0; ks < 2; ks++) {
            uint32_t koff = ks * 32;
            uint32_t aa[4][4], bb[4][4];
            uint32_t a_base = st + (wm * 64 + a_roff) * RSTRIDE + koff + a_koff;
            uint32_t b_base = st + OFF_BH + (wn * 64 + b_roff) * RSTRIDE + koff + b_koff;
            // ---- pass 1: Ah x Bh ----
            #pragma unroll
            for (int mt = 0; mt < 4; mt++) LDSM4(aa[mt], a_base + OFF_AH + mt * 16 * RSTRIDE);
            #pragma unroll
            for (int np = 0; np < 4; np++) LDSM4(bb[np], b_base + np * 16 * RSTRIDE);
            #pragma unroll
            for (int mt = 0; mt < 4; mt++)
                #pragma unroll
                for (int np = 0; np < 4; np++) {
                    MMA16816(acc[mt][2*np+0], aa[mt], bb[np][0], bb[np][1]);
                    MMA16816(acc[mt][2*np+1], aa[mt], bb[np][2], bb[np][3]);
                }
            // ---- pass 2: Al x Bh (reuse bb) ----
            #pragma unroll
            for (int mt = 0; mt < 4; mt++) LDSM4(aa[mt], a_base + OFF_AL + mt * 16 * RSTRIDE);
            #pragma unroll
            for (int mt = 0; mt < 4; mt++)
                #pragma unroll
                for (int np = 0; np < 4; np++) {
                    MMA16816(acc[mt][2*np+0], aa[mt], bb[np][0], bb[np][1]);
                    MMA16816(acc[mt][2*np+1], aa[mt], bb[np][2], bb[np][3]);
                }
        }
        __syncthreads();
        if (ch + 2 < NCHUNK) LOAD_CHUNK(ch + 2, s);
    }

    // ---- epilogue: +bias, *mask, head-split scatter. h constant per warp ----
    int h = blockIdx.x * 4 + wn;
    int r4 = lid >> 2, c2 = (lid & 3) * 2;
    const float* amrow = am + (h & 1) * SEQ;
    #pragma unroll
    for (int mt = 0; mt < 4; mt++) {
        #pragma unroll
        for (int half = 0; half < 2; half++) {
            int m = m0 + wm * 64 + mt * 16 + r4 + half * 8;
            int b_ = m >> 12, sidx = m & 4095;
            float maskv = 1.0f + __ldg(amrow + sidx) * 1e-4f;
            int mbi = b_ * 16 + h;
            float* op = out + ((size_t)mbi * SEQ + sidx) * DH;
            #pragma unroll
            for (int nt = 0; nt < 8; nt++) {
                int e = nt * 8 + c2;
                float2 v;
                v.x = (acc[mt][nt][half*2+0] + __ldg(bias + h * 64 + e))     * maskv;
                v.y = (acc[mt][nt][half*2+1] + __ldg(bias + h * 64 + e + 1)) * maskv;
                *(float2*)(op + e) = v;
            }
        }
    }
    #undef LOAD_CHUNK
}

// ---------------- K2: block means + token counts ----------------
__global__ void k_stats(const float* __restrict__ am) {
    int mb = blockIdx.y, i = blockIdx.x, e = threadIdx.x; // 64 threads
    float tc = 0.0f;
    int amb = (mb & 1) * SEQ + i * BS;
    for (int t = 0; t < BS; t++) tc += 1.0f + am[amb + t] / 10000.0f;
    float den = tc + 1e-6f;
    const float* Qp = g_Q + ((size_t)mb * SEQ + i * BS) * DH + e;
    const float* Kp = g_K + ((size_t)mb * SEQ + i * BS) * DH + e;
    const float* Vp = g_V + ((size_t)mb * SEQ + i * BS) * DH + e;
    float sq = 0, sk = 0, sv = 0;
    for (int t = 0; t < BS; t++) { sq += Qp[t*DH]; sk += Kp[t*DH]; sv += Vp[t*DH]; }
    int o = (mb * NB + i) * DH + e;
    g_Qh[o] = sq / den; g_Kh[o] = sk / den; g_Vh[o] = sv / den;
    if (e == 0) g_tc[mb * NB + i] = tc;
}

// ---------------- K3: low-res logits, row max, lrn ----------------
__global__ __launch_bounds__(128) void k_lowlogit() {
    int mb = blockIdx.x, i = threadIdx.x;
    __shared__ float sK[NB * DH];   // 32KB
    __shared__ float sTc[NB];
    for (int t = i; t < NB * DH; t += 128) sK[t] = g_Kh[mb * NB * DH + t];
    if (i < NB) sTc[i] = g_tc[mb * NB + i];
    __syncthreads();

    float qr[DH];
    #pragma unroll
    for (int k = 0; k < DH; k++) qr[k] = g_Qh[(mb * NB + i) * DH + k];

    float* llrow = g_ll + (mb * NB + i) * NB;
    float rmax = -INFINITY;
    for (int j = 0; j < NB; j++) {
        float d = 0.0f;
        #pragma unroll
        for (int k = 0; k < DH; k++) d += qr[k] * sK[j * DH + k];
        d *= 0.125f;
        llrow[j] = d;                // raw logit (pre-mask); same thread re-reads below
        rmax = fmaxf(rmax, d);       // max BEFORE mask subtraction (matches reference)
    }
    g_rowmax[mb * NB + i] = rmax;
    float tci = sTc[i];
    float* lrow = g_lrn + (mb * NB + i) * NB;
    for (int j = 0; j < NB; j++) {
        float ll = llrow[j];
        if (tci * sTc[j] < 0.5f) ll -= 10000.0f;
        float lr = ll - rmax;
        int dd = i - j; if (dd < 0) dd = -dd;
        if (dd <= 1) lr += 5000.0f;  // DIAG_N=3 band
        llrow[j] = ll;
        lrow[j] = lr;
    }
}

// ---------------- K4: top-512 threshold + per-qb kb lists ----------------
__global__ __launch_bounds__(256) void k_topk() {
    extern __shared__ unsigned skey[];   // 16384 keys = 64KB
    int mb = blockIdx.x, tid = threadIdx.x;
    const float* base = g_lrn + mb * NB * NB;
    __shared__ unsigned sred[256];
    for (int idx = tid; idx < NB * NB; idx += 256) skey[idx] = fkey(base[idx]);
    __syncthreads();
    unsigned lo = 0, hi = 0xFFFFFFFFu;
    while (lo < hi) {
        unsigned mid = (unsigned)(((unsigned long long)lo + (unsigned long long)hi + 1ull) >> 1);
        unsigned c = 0;
        for (int idx = tid; idx < NB * NB; idx += 256) c += (skey[idx] >= mid) ? 1u : 0u;
        sred[tid] = c; __syncthreads();
        for (int off = 128; off; off >>= 1) { if (tid < off) sred[tid] += sred[tid + off]; __syncthreads(); }
        unsigned cnt = sred[0]; __syncthreads();
        if (cnt >= NSEL) lo = mid; else hi = mid - 1;
    }
    if (tid == 0) g_thrkey[mb] = lo;
    for (int idx = tid; idx < NB * NB; idx += 256) {
        if (skey[idx] >= lo) {
            int qb = idx >> 7, kb = idx & 127;
            int p = atomicAdd(&g_qcnt[mb * NB + qb], 1);
            g_qlist[(mb * NB + qb) * NB + p] = kb;
        }
    }
}

// ---------------- K5: fused hi-branch, online softmax per (mb, qb) ----------------
__global__ __launch_bounds__(256) void k_hi(const float* __restrict__ am) {
    int mb = blockIdx.y, qb = blockIdx.x, tid = threadIdx.x;
    int cnt = g_qcnt[mb * NB + qb];
    int q = tid >> 3, g = tid & 7;
    int e0 = g * 8;
    __shared__ float sQ[BS * 68], sK[BS * 68], sV[BS * 68], sL[BS * 33], sMk[BS];
    __shared__ int sList[NB];
    const float* Qg = g_Q + ((size_t)mb * SEQ + qb * BS) * DH;
    for (int t = tid; t < BS * DH / 4; t += 256) {
        int r = t >> 4, cc = (t & 15) * 4;
        *(float4*)&sQ[r * 68 + cc] = ((const float4*)Qg)[t];
    }
    for (int t = tid; t < cnt; t += 256) sList[t] = g_qlist[(mb * NB + qb) * NB + t];
    __syncthreads();

    float m = -1e8f, nsum = 0.0f;
    float acc[8] = {0,0,0,0,0,0,0,0};
    for (int p = 0; p < cnt; p++) {
        int kb = sList[p];
        const float* Kg = g_K + ((size_t)mb * SEQ + kb * BS) * DH;
        const float* Vg = g_V + ((size_t)mb * SEQ + kb * BS) * DH;
        __syncthreads();
        for (int t = tid; t < BS * DH / 4; t += 256) {
            int r = t >> 4, cc = (t & 15) * 4;
            *(float4*)&sK[r * 68 + cc] = ((const float4*)Kg)[t];
            *(float4*)&sV[r * 68 + cc] = ((const float4*)Vg)[t];
        }
        if (tid < BS) sMk[tid] = 1.0f + __ldg(am + (mb & 1) * SEQ + kb * BS + tid) * 1e-4f;
        __syncthreads();
        // k = g + 8*kk -> 8 distinct smem banks across the 8 g-groups (no conflict)
        #pragma unroll
        for (int kk = 0; kk < 4; kk++) {
            int k = g + kk * 8;
            float d = 0.0f;
            #pragma unroll
            for (int e = 0; e < DH; e++) d += sK[k * 68 + e] * sQ[q * 68 + e];
            sL[k * 33 + q] = d * 0.125f;
        }
        __syncthreads();
        float bm = -1e8f;
        #pragma unroll
        for (int k = 0; k < BS; k++) bm = fmaxf(bm, sL[k * 33 + q]);  // unmasked max (matches ref)
        float newm = fmaxf(m, bm);
        float scale = __expf(m - newm);
        m = newm;
        nsum *= scale;
        #pragma unroll
        for (int j = 0; j < 8; j++) acc[j] *= scale;
        #pragma unroll
        for (int k = 0; k < BS; k++) {
            float a = __expf(sL[k * 33 + q] - m - 10000.0f * (1.0f - sMk[k]));
            nsum += a;
            #pragma unroll
            for (int j = 0; j < 8; j++) acc[j] += a * sV[k * 68 + e0 + j];
        }
    }
    float* dst = g_hiout + ((size_t)mb * SEQ + qb * BS + q) * DH + e0;
    #pragma unroll
    for (int j = 0; j < 8; j++) dst[j] = acc[j];
    if (g == 0) {
        g_hinorm[mb * SEQ + qb * BS + q] = nsum;
        g_maxblkf[(mb * NB + qb) * BS + q] = m;
    }
}

// ---------------- K7: low-res branch (selected blocks suppressed) ----------------
__global__ __launch_bounds__(128) void k_low() {
    int mb = blockIdx.y, i = blockIdx.x, j = threadIdx.x;
    __shared__ float sA[NB];
    __shared__ float sred[NB];
    float thr  = fdecode(g_thrkey[mb]);
    float rmax = g_rowmax[mb * NB + i];
    float ll = g_ll [(mb * NB + i) * NB + j];
    float lr = g_lrn[(mb * NB + i) * NB + j];
    float a = __expf(ll - rmax - ((lr >= thr) ? 10000.0f : 0.0f)) * g_tc[mb * NB + j];
    sA[j] = a; sred[j] = a;
    __syncthreads();
    for (int off = 64; off; off >>= 1) { if (j < off) sred[j] += sred[j + off]; __syncthreads(); }
    if (j == 0) g_lownorm[mb * NB + i] = sred[0];
    if (j < DH) {
        float acc = 0.0f;
        for (int t = 0; t < NB; t++) acc += sA[t] * g_Vh[(mb * NB + t) * DH + j];
        g_lowout[(mb * NB + i) * DH + j] = acc;
    }
}

// ---------------- K8: final combine + head merge ----------------
__global__ void k_combine(const float* __restrict__ am, float* __restrict__ out) {
    int mb = blockIdx.y;
    int s  = blockIdx.x * 4 + (threadIdx.x >> 6);
    int e  = threadIdx.x & 63;
    int i = s >> 5, t = s & 31;
    float maskv = 1.0f + am[(mb & 1) * SEQ + s] / 10000.0f;
    float rm = g_rowmax[mb * NB + i];
    float mv = g_maxblkf[(mb * NB + i) * BS + t];
    float lc = (rm - mv) * maskv;
    float locorr = __expf(fminf(lc, 0.0f));
    float hicorr = __expf(-fmaxf(lc, 0.0f));
    float hn = g_hinorm[mb * SEQ + s] * hicorr;
    float ln = g_lownorm[mb * NB + i] * locorr;
    float den = hn + ln + 1e-6f;
    float v = (g_hiout[((size_t)mb * SEQ + s) * DH + e] * hicorr
             + g_lowout[(mb * NB + i) * DH + e] * locorr) / den * maskv;
    int b = mb >> 4, h = mb & 15;
    out[((size_t)b * SEQ + s) * HDIM + h * DH + e] = v;
}

// ---------------- launch ----------------
extern "C" void kernel_launch(void* const* d_in, const int* in_sizes, int n_in,
                              void* d_out, int out_size) {
    const float* X  = (const float*)d_in[0];
    const float* am = (const float*)d_in[1];
    const float* wq = (const float*)d_in[2];
    const float* bq = (const float*)d_in[3];
    const float* wk = (const float*)d_in[4];
    const float* bk = (const float*)d_in[5];
    const float* wv = (const float*)d_in[6];
    const float* bv = (const float*)d_in[7];
    float* out = (float*)d_out;

    void *pXhi, *pXlo, *pWhi, *pWlo;
    cudaGetSymbolAddress(&pXhi, g_Xhi);
    cudaGetSymbolAddress(&pXlo, g_Xlo);
    cudaGetSymbolAddress(&pWhi, g_Whi);
    cudaGetSymbolAddress(&pWlo, g_Wlo);

    cudaFuncSetAttribute(k_gemm_mma, cudaFuncAttributeMaxDynamicSharedMemorySize, GEMM_SMEM);
    cudaFuncSetAttribute(k_topk, cudaFuncAttributeMaxDynamicSharedMemorySize, 65536);

    int nx4 = MROWS * HDIM / 4;
    int nw4 = HDIM * HDIM / 4;
    k_split<<<(nx4 + 255) / 256, 256>>>((const float4*)X,  (__half2*)pXhi, (__half2*)pXlo, nx4);
    k_split<<<(nw4 + 255) / 256, 256>>>((const float4*)wq, (__half2*)pWhi, (__half2*)pWlo, nw4);
    k_split<<<(nw4 + 255) / 256, 256>>>((const float4*)wk,
        (__half2*)((char*)pWhi + (size_t)HDIM*HDIM*2), (__half2*)((char*)pWlo + (size_t)HDIM*HDIM*2), nw4);
    k_split<<<(nw4 + 255) / 256, 256>>>((const float4*)wv,
        (__half2*)((char*)pWhi + (size_t)2*HDIM*HDIM*2), (__half2*)((char*)pWlo + (size_t)2*HDIM*HDIM*2), nw4);
    k_zero<<<(MB * NB + 255) / 256, 256>>>();

    k_gemm_mma<<<dim3(HDIM / 256, MROWS / 128, 3), 256, GEMM_SMEM>>>(am, bq, bk, bv);

    k_stats<<<dim3(NB, MB), 64>>>(am);
    k_lowlogit<<<MB, 128>>>();
    k_topk<<<MB, 256, 65536>>>();
    k_hi<<<dim3(NB, MB), 256>>>(am);
    k_low<<<dim3(NB, MB), 128>>>();
    k_combine<<<dim3(SEQ / 4, MB), 256>>>(am, out);
}